// round 11
// baseline (speedup 1.0000x reference)
#include <cuda_runtime.h>
#include <cuda_fp16.h>
#include <cstdint>

// SpikingMLP:
//   GEMM1 (fp16 m16n8k16 3-pass, w_up*2^8, CTA 128x256, warp 64x64):
//       rate = spike_rate(x @ w_up^T)
//   GEMM2 (fp16 single pass, w_down*2^4, CTA 128x128): out = rate @ w_down^T / 2^4
//   rate_per_unit via exact atomic column sums in GEMM1 epilogue.

namespace cfg {
constexpr int M  = 4096;
constexpr int Dd = 1024;
constexpr int Ff = 4096;
}

__device__ uint4 g_axh[(size_t)32 * 32 * 512];           // A hi  [kc][mtile][16][lane]
__device__ uint4 g_axl[(size_t)32 * 32 * 512];           // A lo
__device__ uint4 g_buh[(size_t)32 * 32 * 512];           // B hi  [kc][ntile][nb][kb][lane] (uint2)
__device__ uint4 g_bul[(size_t)32 * 32 * 512];           // B lo
__device__ uint4 g_dw[(size_t)cfg::Dd * cfg::Ff / 8];    // w_down * 2^4
__device__ uint4 g_ratep[(size_t)cfg::M * cfg::Ff / 8];  // rate fp16, GEMM2-A packed
__device__ float g_colsum[cfg::Ff];

// ------------------------------------------------------------------ helpers
__device__ __forceinline__ uint32_t pack_h2(float a, float b) {
    __half2 p = __floats2half2_rn(a, b);
    return *(uint32_t*)&p;
}
__device__ __forceinline__ void mma_f16(float c[4], const uint4& a, const uint2& b) {
    asm volatile(
        "mma.sync.aligned.m16n8k16.row.col.f32.f16.f16.f32 "
        "{%0,%1,%2,%3}, {%4,%5,%6,%7}, {%8,%9}, {%0,%1,%2,%3};"
        : "+f"(c[0]), "+f"(c[1]), "+f"(c[2]), "+f"(c[3])
        : "r"(a.x), "r"(a.y), "r"(a.z), "r"(a.w), "r"(b.x), "r"(b.y));
}
__device__ __forceinline__ void cp16(uint32_t sdst, const void* gsrc) {
    asm volatile("cp.async.cg.shared.global [%0], [%1], 16;" :: "r"(sdst), "l"(gsrc));
}
#define CP_COMMIT() asm volatile("cp.async.commit_group;" ::: "memory")

__device__ __forceinline__ float spike_rate_of(float h, float be, int T, float invT) {
    float v = 0.0f; int cnt = 0;
    for (int t = 0; t < T; t++) {
        v = be * v + h;
        if (v > 1.0f) { cnt++; v -= 1.0f; }
    }
    return (float)cnt * invT;
}

// -------------------------------------------------------------- pack kernels
__global__ void pack_a_f16(const float* __restrict__ src,
                           uint4* __restrict__ hi, uint4* __restrict__ lo)
{
    if (blockIdx.x < 16) g_colsum[blockIdx.x * 256 + threadIdx.x] = 0.0f;  // fused zero
    constexpr int K = 1024, KB = K / 16;
    const int wg   = (blockIdx.x * 256 + threadIdx.x) >> 5;
    const int lane = threadIdx.x & 31;
    const int rbg = wg / KB, kbg = wg % KB;
    const int gq = lane >> 2, tq = lane & 3;
    const float* s = src + (size_t)(rbg * 16) * K + kbg * 16;
    float v[8];
    v[0] = s[(size_t)gq * K + 2 * tq];       v[1] = s[(size_t)gq * K + 2 * tq + 1];
    v[2] = s[(size_t)(gq + 8) * K + 2 * tq]; v[3] = s[(size_t)(gq + 8) * K + 2 * tq + 1];
    v[4] = s[(size_t)gq * K + 2 * tq + 8];   v[5] = s[(size_t)gq * K + 2 * tq + 9];
    v[6] = s[(size_t)(gq + 8) * K + 2 * tq + 8]; v[7] = s[(size_t)(gq + 8) * K + 2 * tq + 9];
    float h[8], l[8];
    #pragma unroll
    for (int i = 0; i < 8; i++) {
        h[i] = __half2float(__float2half_rn(v[i]));
        l[i] = v[i] - h[i];
    }
    const int mtile = rbg >> 3, rb = rbg & 7, kc = kbg >> 1, kb = kbg & 1;
    const size_t idx = (((size_t)kc * 32 + mtile) * 16 + rb * 2 + kb) * 32 + lane;
    hi[idx] = make_uint4(pack_h2(h[0], h[1]), pack_h2(h[2], h[3]),
                         pack_h2(h[4], h[5]), pack_h2(h[6], h[7]));
    lo[idx] = make_uint4(pack_h2(l[0], l[1]), pack_h2(l[2], l[3]),
                         pack_h2(l[4], l[5]), pack_h2(l[6], l[7]));
}

__global__ void pack_b_f16(const float* __restrict__ src,
                           uint2* __restrict__ hi, uint2* __restrict__ lo)
{
    constexpr int K = 1024, KB = K / 16;
    const int wg   = (blockIdx.x * 256 + threadIdx.x) >> 5;
    const int lane = threadIdx.x & 31;
    const int nbg = wg / KB, kbg = wg % KB;
    const int gq = lane >> 2, tq = lane & 3;
    const float* s = src + (size_t)(nbg * 8 + gq) * K + kbg * 16;
    const float v0 = s[2 * tq] * 256.0f,     v1 = s[2 * tq + 1] * 256.0f;
    const float v2 = s[2 * tq + 8] * 256.0f, v3 = s[2 * tq + 9] * 256.0f;
    const float h0 = __half2float(__float2half_rn(v0));
    const float h1 = __half2float(__float2half_rn(v1));
    const float h2 = __half2float(__float2half_rn(v2));
    const float h3 = __half2float(__float2half_rn(v3));
    const int ntile = nbg >> 4, nb = nbg & 15, kc = kbg >> 1, kb = kbg & 1;
    const size_t idx = ((((size_t)kc * 32 + ntile) * 16 + nb) * 2 + kb) * 32 + lane;
    hi[idx] = make_uint2(pack_h2(h0, h1), pack_h2(h2, h3));
    lo[idx] = make_uint2(pack_h2(v0 - h0, v1 - h1), pack_h2(v2 - h2, v3 - h3));
}

__global__ void pack_w_down_f16(const float* __restrict__ src,
                                uint2* __restrict__ dst)
{
    constexpr int K = 4096, KB16 = K / 16;
    const int wg   = (blockIdx.x * 256 + threadIdx.x) >> 5;
    const int lane = threadIdx.x & 31;
    const int nbg = wg / KB16, kbg = wg % KB16;
    const int gq = lane >> 2, tq = lane & 3;
    const float* s = src + (size_t)(nbg * 8 + gq) * K + kbg * 16;
    const float v0 = s[2 * tq] * 16.0f,     v1 = s[2 * tq + 1] * 16.0f;
    const float v2 = s[2 * tq + 8] * 16.0f, v3 = s[2 * tq + 9] * 16.0f;
    const int ntile = nbg >> 4, nb = nbg & 15, kc = kbg >> 2, kb = kbg & 3;
    const size_t idx = ((((size_t)kc * 8 + ntile) * 16 + nb) * 4 + kb) * 32 + lane;
    dst[idx] = make_uint2(pack_h2(v0, v1), pack_h2(v2, v3));
}

__global__ void finalize_rpu(float* __restrict__ rpu) {
    const int f = blockIdx.x * 256 + threadIdx.x;
    rpu[f] = g_colsum[f] * (1.0f / (float)cfg::M);   // exact
}

// ------------------------------- GEMM1 (fp16, 3 passes, CTA 128x256, warp 64x64)
__global__ __launch_bounds__(256, 1)
void tc_gemm1(const float* __restrict__ beta, const int* __restrict__ Tptr)
{
    constexpr int ATILE = 8192;                     // bytes: 128x32 fp16
    constexpr int BTILE = 16384;                    // bytes: 256x32 fp16
    constexpr int STAGE = 2 * ATILE + 2 * BTILE;    // Ah,Al,Bh,Bl = 49152
    constexpr int NC = cfg::Dd / 32;                // 32
    constexpr int STAGES = 3;                       // 144 KB
    extern __shared__ char smc[];
    float* sm = (float*)smc;

    const int tid = threadIdx.x, lane = tid & 31, wid = tid >> 5;
    const int gq = lane >> 2, tq = lane & 3;
    const int mtile = blockIdx.y;                   // 0..31
    const int npair = blockIdx.x;                   // 0..15 (256-col blocks)
    const int colBase = npair * 256;
    const int wm = wid & 1, wn = wid >> 1;          // 2(M) x 4(N), warp tile 64x64
    const uint32_t sb = (uint32_t)__cvta_generic_to_shared(smc);

    const uint4* pAh = g_axh + (size_t)mtile * 512;
    const uint4* pAl = g_axl + (size_t)mtile * 512;
    const uint4* pBh = g_buh + (size_t)npair * 1024;   // 2 ntiles contiguous
    const uint4* pBl = g_bul + (size_t)npair * 1024;
    constexpr size_t strideKC = (size_t)32 * 512;      // 16384 uint4 per kc (A and B)

    auto stage_load = [&](int c, int st) {
        const uint32_t d = sb + (uint32_t)st * STAGE;
        const size_t o = (size_t)c * strideKC;
        #pragma unroll
        for (int q = 0; q < 2; q++) {
            const int i = q * 256 + tid;
            cp16(d + i * 16,         pAh + o + i);
            cp16(d + ATILE + i * 16, pAl + o + i);
        }
        #pragma unroll
        for (int q = 0; q < 4; q++) {
            const int i = q * 256 + tid;
            cp16(d + 2 * ATILE + i * 16,         pBh + o + i);
            cp16(d + 2 * ATILE + BTILE + i * 16, pBl + o + i);
        }
    };

    float acc[4][8][4];
    #pragma unroll
    for (int mi = 0; mi < 4; mi++)
        #pragma unroll
        for (int ni = 0; ni < 8; ni++)
            #pragma unroll
            for (int q = 0; q < 4; q++) acc[mi][ni][q] = 0.0f;

    #pragma unroll
    for (int s = 0; s < STAGES; s++) { stage_load(s, s); CP_COMMIT(); }

    int st = 0;
    for (int c = 0; c < NC; c++) {
        asm volatile("cp.async.wait_group 2;" ::: "memory");
        __syncthreads();
        const uint4* ahs = (const uint4*)(smc + st * STAGE);
        const uint4* als = ahs + 512;
        const uint2* bhs = (const uint2*)(smc + st * STAGE + 2 * ATILE);
        const uint2* bls = bhs + 2048;

        #pragma unroll
        for (int ks = 0; ks < 2; ks++) {
            uint2 bh[8];
            #pragma unroll
            for (int ni = 0; ni < 8; ni++)
                bh[ni] = bhs[((wn * 8 + ni) * 2 + ks) * 32 + lane];
            uint4 ah4[4];
            #pragma unroll
            for (int mi = 0; mi < 4; mi++)
                ah4[mi] = ahs[((wm * 4 + mi) * 2 + ks) * 32 + lane];
            // pass 1: hh (32 independent mma)
            #pragma unroll
            for (int mi = 0; mi < 4; mi++)
                #pragma unroll
                for (int ni = 0; ni < 8; ni++) mma_f16(acc[mi][ni], ah4[mi], bh[ni]);
            // pass 2: hl
            uint2 bl[8];
            #pragma unroll
            for (int ni = 0; ni < 8; ni++)
                bl[ni] = bls[((wn * 8 + ni) * 2 + ks) * 32 + lane];
            #pragma unroll
            for (int mi = 0; mi < 4; mi++)
                #pragma unroll
                for (int ni = 0; ni < 8; ni++) mma_f16(acc[mi][ni], ah4[mi], bl[ni]);
            // pass 3: lh
            uint4 al4[4];
            #pragma unroll
            for (int mi = 0; mi < 4; mi++)
                al4[mi] = als[((wm * 4 + mi) * 2 + ks) * 32 + lane];
            #pragma unroll
            for (int mi = 0; mi < 4; mi++)
                #pragma unroll
                for (int ni = 0; ni < 8; ni++) mma_f16(acc[mi][ni], al4[mi], bh[ni]);
        }
        __syncthreads();
        if (c + STAGES < NC) stage_load(c + STAGES, st);
        CP_COMMIT();
        st = (st + 1 == STAGES) ? 0 : st + 1;
    }

    // ---------------- epilogue: unscale 2^-8, spike -> smem (stride 260) ----------------
    constexpr float SC = 1.0f / 256.0f;
    const int   T    = *Tptr;
    const float invT = 1.0f / (float)T;
    __syncthreads();
    #pragma unroll
    for (int ni = 0; ni < 8; ni++) {
        const int cl = wn * 64 + ni * 8 + 2 * tq;
        const float be0 = beta[colBase + cl];
        const float be1 = beta[colBase + cl + 1];
        #pragma unroll
        for (int mi = 0; mi < 4; mi++) {
            const int r0 = wm * 64 + mi * 16 + gq;
            sm[r0 * 260 + cl]           = spike_rate_of(acc[mi][ni][0] * SC, be0, T, invT);
            sm[r0 * 260 + cl + 1]       = spike_rate_of(acc[mi][ni][1] * SC, be1, T, invT);
            sm[(r0 + 8) * 260 + cl]     = spike_rate_of(acc[mi][ni][2] * SC, be0, T, invT);
            sm[(r0 + 8) * 260 + cl + 1] = spike_rate_of(acc[mi][ni][3] * SC, be1, T, invT);
        }
    }
    __syncthreads();
    // exact column sums (1 thread per column; multiples of 1/8 -> order-free)
    {
        float s = 0.0f;
        #pragma unroll 8
        for (int r = 0; r < 128; r++) s += sm[r * 260 + tid];
        atomicAdd(&g_colsum[colBase + tid], s);
    }
    // write rate (exact fp16) in GEMM2-A packed layout, 2 x 128-col halves
    #pragma unroll
    for (int ch = 0; ch < 2; ch++) {
        #pragma unroll
        for (int i = 0; i < 8; i++) {
            const int idx = i * 256 + tid;
            const int l2  = idx & 31;
            const int t2  = idx >> 5;
            const int kcj = t2 >> 5;
            const int pos = t2 & 31;
            const int g2 = l2 >> 2, q2 = l2 & 3;
            const int ml = (pos >> 2) * 16;
            const int fl = ch * 128 + kcj * 64 + (pos & 3) * 16;
            const int ra = ml + g2, rb2 = ml + g2 + 8;
            const int c0 = fl + 2 * q2, c8 = fl + 2 * q2 + 8;
            uint4 v;
            v.x = pack_h2(sm[ra * 260 + c0],  sm[ra * 260 + c0 + 1]);
            v.y = pack_h2(sm[rb2 * 260 + c0], sm[rb2 * 260 + c0 + 1]);
            v.z = pack_h2(sm[ra * 260 + c8],  sm[ra * 260 + c8 + 1]);
            v.w = pack_h2(sm[rb2 * 260 + c8], sm[rb2 * 260 + c8 + 1]);
            g_ratep[((size_t)((colBase + ch * 128) / 64 + kcj) * 32 + mtile) * 1024
                    + pos * 32 + l2] = v;
        }
    }
}

// --------------------------------------------- GEMM2 (fp16, single pass; = R9)
__global__ __launch_bounds__(256, 2)
void tc_gemm2(const uint4* __restrict__ A, const uint4* __restrict__ B,
              float* __restrict__ C)
{
    constexpr int TILE = 16384;
    constexpr int STAGE = 2 * TILE;
    constexpr int NC = cfg::Ff / 64;
    constexpr int STAGES = 3;
    extern __shared__ char smc[];

    const int tid = threadIdx.x, lane = tid & 31, wid = tid >> 5;
    const int gq = lane >> 2, tq = lane & 3;
    const int mtile = blockIdx.y, ntile = blockIdx.x;
    const int rowBase = mtile * 128, colBase = ntile * 128;
    const int rbb = (wid & 1) * 4, nbb = (wid >> 1) * 4;
    const int wm = (wid & 1) * 64, wn = (wid >> 1) * 32;
    const uint32_t sb = (uint32_t)__cvta_generic_to_shared(smc);

    const uint4* pA = A + (size_t)mtile * 1024;
    const uint4* pB = B + (size_t)ntile * 1024;
    constexpr size_t strideA = (size_t)32 * 1024;
    constexpr size_t strideB = (size_t)8 * 1024;

    auto stage_load = [&](int c, int st) {
        const uint32_t d = sb + (uint32_t)st * STAGE;
        const uint4* a = pA + (size_t)c * strideA;
        const uint4* b = pB + (size_t)c * strideB;
        #pragma unroll
        for (int q = 0; q < 4; q++) {
            const int idx = q * 256 + tid;
            cp16(d + idx * 16, a + idx);
            cp16(d + TILE + idx * 16, b + idx);
        }
    };

    float acc[4][4][4];
    #pragma unroll
    for (int mi = 0; mi < 4; mi++)
        #pragma unroll
        for (int ni = 0; ni < 4; ni++)
            #pragma unroll
            for (int q = 0; q < 4; q++) acc[mi][ni][q] = 0.0f;

    #pragma unroll
    for (int s = 0; s < STAGES; s++) { stage_load(s, s); CP_COMMIT(); }

    int st = 0;
    for (int c = 0; c < NC; c++) {
        asm volatile("cp.async.wait_group 2;" ::: "memory");
        __syncthreads();
        const uint4* ahs = (const uint4*)(smc + st * STAGE);
        const uint2* bhs = (const uint2*)(smc + st * STAGE + TILE);

        #pragma unroll
        for (int ks = 0; ks < 4; ks++) {
            uint2 bh[4];
            #pragma unroll
            for (int ni = 0; ni < 4; ni++)
                bh[ni] = bhs[((nbb + ni) * 4 + ks) * 32 + lane];
            #pragma unroll
            for (int mp = 0; mp < 2; mp++) {
                const int m0 = 2 * mp, m1 = 2 * mp + 1;
                const uint4 a0 = ahs[((rbb + m0) * 4 + ks) * 32 + lane];
                const uint4 a1 = ahs[((rbb + m1) * 4 + ks) * 32 + lane];
                #pragma unroll
                for (int ni = 0; ni < 4; ni++) mma_f16(acc[m0][ni], a0, bh[ni]);
                #pragma unroll
                for (int ni = 0; ni < 4; ni++) mma_f16(acc[m1][ni], a1, bh[ni]);
            }
        }
        __syncthreads();
        if (c + STAGES < NC) stage_load(c + STAGES, st);
        CP_COMMIT();
        st = (st + 1 == STAGES) ? 0 : st + 1;
    }

    constexpr float SC = 1.0f / 16.0f;
    #pragma unroll
    for (int ni = 0; ni < 4; ni++) {
        const int cglob = colBase + wn + ni * 8 + 2 * tq;
        #pragma unroll
        for (int mi = 0; mi < 4; mi++) {
            const int r0 = rowBase + wm + mi * 16 + gq;
            *(float2*)(C + (size_t)r0 * cfg::Dd + cglob) =
                make_float2(acc[mi][ni][0] * SC, acc[mi][ni][1] * SC);
            *(float2*)(C + (size_t)(r0 + 8) * cfg::Dd + cglob) =
                make_float2(acc[mi][ni][2] * SC, acc[mi][ni][3] * SC);
        }
    }
}

// -------------------------------------------------------------------- launch
extern "C" void kernel_launch(void* const* d_in, const int* in_sizes, int n_in,
                              void* d_out, int out_size)
{
    const float* x      = (const float*)d_in[0];
    const float* w_up   = (const float*)d_in[1];
    const float* w_down = (const float*)d_in[2];
    const float* beta   = (const float*)d_in[3];
    const int*   Tptr   = (const int*)d_in[4];

    float* out = (float*)d_out;
    float* rpu = out + (size_t)cfg::M * cfg::Dd;

    uint4 *axh, *axl, *buh, *bul, *dw, *ratep;
    cudaGetSymbolAddress((void**)&axh, g_axh);
    cudaGetSymbolAddress((void**)&axl, g_axl);
    cudaGetSymbolAddress((void**)&buh, g_buh);
    cudaGetSymbolAddress((void**)&bul, g_bul);
    cudaGetSymbolAddress((void**)&dw, g_dw);
    cudaGetSymbolAddress((void**)&ratep, g_ratep);

    pack_a_f16<<<2048, 256>>>(x, axh, axl);                      // + colsum zero
    pack_b_f16<<<4096, 256>>>(w_up, (uint2*)buh, (uint2*)bul);
    pack_w_down_f16<<<4096, 256>>>(w_down, (uint2*)dw);

    constexpr int SMEM1 = 3 * 49152;       // 147456 B
    constexpr int SMEM2 = 3 * 2 * 16384;   // 98304 B
    cudaFuncSetAttribute(tc_gemm1, cudaFuncAttributeMaxDynamicSharedMemorySize, SMEM1);
    cudaFuncSetAttribute(tc_gemm2, cudaFuncAttributeMaxDynamicSharedMemorySize, SMEM2);

    // GEMM1: grid (F/256, M/128) = (16, 32)
    tc_gemm1<<<dim3(cfg::Ff / 256, cfg::M / 128), 256, SMEM1>>>(beta, Tptr);

    finalize_rpu<<<cfg::Ff / 256, 256>>>(rpu);

    // GEMM2: grid (Dd/128, M/128) = (8, 32)
    tc_gemm2<<<dim3(cfg::Dd / 128, cfg::M / 128), 256, SMEM2>>>(ratep, dw, out);
}

// round 12
// speedup vs baseline: 1.0439x; 1.0439x over previous
#include <cuda_runtime.h>
#include <cuda_fp16.h>
#include <cstdint>

// SpikingMLP, fused persistent version:
//   pack (1 kernel): x -> fp16 hi/lo frags, w_up*2^8 -> fp16 hi/lo, w_down*2^4 -> fp16
//   tc_fused (296 persistent CTAs, atomic work queue):
//     items [0,1024): GEMM1 tiles (fp16 3-pass) -> rate (exact fp16) + colsums
//     items [1024,1280): GEMM2 tiles (fp16 1-pass), gated on per-row counters
//   finalize_rpu: rate_per_unit = colsum / M (exact).

namespace cfg {
constexpr int M  = 4096;
constexpr int Dd = 1024;
constexpr int Ff = 4096;
}

__device__ uint4 g_axh[(size_t)32 * 32 * 512];
__device__ uint4 g_axl[(size_t)32 * 32 * 512];
__device__ uint4 g_buh[(size_t)32 * 32 * 512];
__device__ uint4 g_bul[(size_t)32 * 32 * 512];
__device__ uint4 g_dw[(size_t)cfg::Dd * cfg::Ff / 8];    // w_down * 2^4
__device__ uint4 g_ratep[(size_t)cfg::M * cfg::Ff / 8];  // rate fp16, GEMM2-A packed
__device__ float g_colsum[cfg::Ff];
__device__ int   g_ctr;
__device__ int   g_rowdone[32];

// ------------------------------------------------------------------ helpers
__device__ __forceinline__ uint32_t pack_h2(float a, float b) {
    __half2 p = __floats2half2_rn(a, b);
    return *(uint32_t*)&p;
}
__device__ __forceinline__ void mma_f16(float c[4], const uint4& a, const uint2& b) {
    asm volatile(
        "mma.sync.aligned.m16n8k16.row.col.f32.f16.f16.f32 "
        "{%0,%1,%2,%3}, {%4,%5,%6,%7}, {%8,%9}, {%0,%1,%2,%3};"
        : "+f"(c[0]), "+f"(c[1]), "+f"(c[2]), "+f"(c[3])
        : "r"(a.x), "r"(a.y), "r"(a.z), "r"(a.w), "r"(b.x), "r"(b.y));
}
__device__ __forceinline__ void cp16(uint32_t sdst, const void* gsrc) {
    asm volatile("cp.async.cg.shared.global [%0], [%1], 16;" :: "r"(sdst), "l"(gsrc));
}
#define CP_COMMIT() asm volatile("cp.async.commit_group;" ::: "memory")
#define CP_WAIT2()  asm volatile("cp.async.wait_group 2;" ::: "memory")

__device__ __forceinline__ float spike_rate_of(float h, float be, int T, float invT) {
    float v = 0.0f; int cnt = 0;
    for (int t = 0; t < T; t++) {
        v = be * v + h;
        if (v > 1.0f) { cnt++; v -= 1.0f; }
    }
    return (float)cnt * invT;
}

// ----------------------------------------------------------- fused pack kernel
// blocks [0,2048): pack x | [2048,6144): pack w_up | [6144,10240): pack w_down
__global__ void pack_all(const float* __restrict__ x,
                         const float* __restrict__ w_up,
                         const float* __restrict__ w_down)
{
    const int bid = blockIdx.x;
    const int tid = threadIdx.x;
    if (bid == 0 && tid == 0) g_ctr = 0;
    if (bid == 1 && tid < 32) g_rowdone[tid] = 0;
    if (bid < 16) g_colsum[bid * 256 + tid] = 0.0f;

    const int lane = tid & 31;
    const int gq = lane >> 2, tq = lane & 3;

    if (bid < 2048) {                         // ---- x -> A hi/lo frags
        constexpr int K = 1024, KB = K / 16;
        const int wg  = (bid * 256 + tid) >> 5;
        const int rbg = wg / KB, kbg = wg % KB;
        const float* s = x + (size_t)(rbg * 16) * K + kbg * 16;
        float v[8];
        v[0] = s[(size_t)gq * K + 2 * tq];       v[1] = s[(size_t)gq * K + 2 * tq + 1];
        v[2] = s[(size_t)(gq + 8) * K + 2 * tq]; v[3] = s[(size_t)(gq + 8) * K + 2 * tq + 1];
        v[4] = s[(size_t)gq * K + 2 * tq + 8];   v[5] = s[(size_t)gq * K + 2 * tq + 9];
        v[6] = s[(size_t)(gq + 8) * K + 2 * tq + 8]; v[7] = s[(size_t)(gq + 8) * K + 2 * tq + 9];
        float h[8], l[8];
        #pragma unroll
        for (int i = 0; i < 8; i++) {
            h[i] = __half2float(__float2half_rn(v[i]));
            l[i] = v[i] - h[i];
        }
        const int mtile = rbg >> 3, rb = rbg & 7, kc = kbg >> 1, kb = kbg & 1;
        const size_t idx = (((size_t)kc * 32 + mtile) * 16 + rb * 2 + kb) * 32 + lane;
        g_axh[idx] = make_uint4(pack_h2(h[0], h[1]), pack_h2(h[2], h[3]),
                                pack_h2(h[4], h[5]), pack_h2(h[6], h[7]));
        g_axl[idx] = make_uint4(pack_h2(l[0], l[1]), pack_h2(l[2], l[3]),
                                pack_h2(l[4], l[5]), pack_h2(l[6], l[7]));
    } else if (bid < 6144) {                  // ---- w_up * 2^8 -> B hi/lo frags
        constexpr int K = 1024, KB = K / 16;
        const int wg  = ((bid - 2048) * 256 + tid) >> 5;
        const int nbg = wg / KB, kbg = wg % KB;
        const float* s = w_up + (size_t)(nbg * 8 + gq) * K + kbg * 16;
        const float v0 = s[2 * tq] * 256.0f,     v1 = s[2 * tq + 1] * 256.0f;
        const float v2 = s[2 * tq + 8] * 256.0f, v3 = s[2 * tq + 9] * 256.0f;
        const float h0 = __half2float(__float2half_rn(v0));
        const float h1 = __half2float(__float2half_rn(v1));
        const float h2 = __half2float(__float2half_rn(v2));
        const float h3 = __half2float(__float2half_rn(v3));
        const int ntile = nbg >> 4, nb = nbg & 15, kc = kbg >> 1, kb = kbg & 1;
        const size_t idx = ((((size_t)kc * 32 + ntile) * 16 + nb) * 2 + kb) * 32 + lane;
        ((uint2*)g_buh)[idx] = make_uint2(pack_h2(h0, h1), pack_h2(h2, h3));
        ((uint2*)g_bul)[idx] = make_uint2(pack_h2(v0 - h0, v1 - h1), pack_h2(v2 - h2, v3 - h3));
    } else {                                  // ---- w_down * 2^4 -> fp16 frags
        constexpr int K = 4096, KB16 = K / 16;
        const int wg  = ((bid - 6144) * 256 + tid) >> 5;
        const int nbg = wg / KB16, kbg = wg % KB16;
        const float* s = w_down + (size_t)(nbg * 8 + gq) * K + kbg * 16;
        const float v0 = s[2 * tq] * 16.0f,     v1 = s[2 * tq + 1] * 16.0f;
        const float v2 = s[2 * tq + 8] * 16.0f, v3 = s[2 * tq + 9] * 16.0f;
        const int ntile = nbg >> 4, nb = nbg & 15, kc = kbg >> 2, kb = kbg & 3;
        const size_t idx = ((((size_t)kc * 8 + ntile) * 16 + nb) * 4 + kb) * 32 + lane;
        ((uint2*)g_dw)[idx] = make_uint2(pack_h2(v0, v1), pack_h2(v2, v3));
    }
}

__global__ void finalize_rpu(float* __restrict__ rpu) {
    const int f = blockIdx.x * 256 + threadIdx.x;
    rpu[f] = g_colsum[f] * (1.0f / (float)cfg::M);   // exact
}

// ------------------------------------------------------ GEMM1 tile (R9 body)
__device__ __forceinline__
void gemm1_tile(char* smc, int mtile, int ntile,
                const float* __restrict__ beta, const int* __restrict__ Tptr)
{
    constexpr int TILE  = 8192;                  // 128x32 fp16
    constexpr int STAGE = 4 * TILE;              // Ah, Al, Bh, Bl
    constexpr int NC    = cfg::Dd / 32;          // 32
    constexpr int STAGES = 3;
    float* sm = (float*)smc;

    const int tid = threadIdx.x, lane = tid & 31, wid = tid >> 5;
    const int gq = lane >> 2, tq = lane & 3;
    const int colBase = ntile * 128;
    const int rbb = (wid & 1) * 4, nbb = (wid >> 1) * 4;
    const int wm = (wid & 1) * 64, wn = (wid >> 1) * 32;
    const uint32_t sb = (uint32_t)__cvta_generic_to_shared(smc);

    const uint4* pAh = g_axh + (size_t)mtile * 512;
    const uint4* pAl = g_axl + (size_t)mtile * 512;
    const uint4* pBh = g_buh + (size_t)ntile * 512;
    const uint4* pBl = g_bul + (size_t)ntile * 512;
    constexpr size_t strideKC = (size_t)32 * 512;

    auto stage_load = [&](int c, int st) {
        const uint32_t d = sb + (uint32_t)st * STAGE;
        const size_t o = (size_t)c * strideKC;
        #pragma unroll
        for (int q = 0; q < 2; q++) {
            const int idx = q * 256 + tid;
            cp16(d + idx * 16,            pAh + o + idx);
            cp16(d + TILE + idx * 16,     pAl + o + idx);
            cp16(d + 2 * TILE + idx * 16, pBh + o + idx);
            cp16(d + 3 * TILE + idx * 16, pBl + o + idx);
        }
    };

    float acc[4][4][4];
    #pragma unroll
    for (int mi = 0; mi < 4; mi++)
        #pragma unroll
        for (int ni = 0; ni < 4; ni++)
            #pragma unroll
            for (int q = 0; q < 4; q++) acc[mi][ni][q] = 0.0f;

    #pragma unroll
    for (int s = 0; s < STAGES; s++) { stage_load(s, s); CP_COMMIT(); }

    int st = 0;
    for (int c = 0; c < NC; c++) {
        CP_WAIT2();
        __syncthreads();
        const uint4* ahs = (const uint4*)(smc + st * STAGE);
        const uint4* als = (const uint4*)(smc + st * STAGE + TILE);
        const uint2* bhs = (const uint2*)(smc + st * STAGE + 2 * TILE);
        const uint2* bls = (const uint2*)(smc + st * STAGE + 3 * TILE);

        #pragma unroll
        for (int ks = 0; ks < 2; ks++) {
            uint2 bh[4], bl[4];
            #pragma unroll
            for (int ni = 0; ni < 4; ni++) {
                bh[ni] = bhs[((nbb + ni) * 2 + ks) * 32 + lane];
                bl[ni] = bls[((nbb + ni) * 2 + ks) * 32 + lane];
            }
            #pragma unroll
            for (int mp = 0; mp < 2; mp++) {
                const int m0 = 2 * mp, m1 = 2 * mp + 1;
                const uint4 a0 = ahs[((rbb + m0) * 2 + ks) * 32 + lane];
                const uint4 a1 = ahs[((rbb + m1) * 2 + ks) * 32 + lane];
                #pragma unroll
                for (int ni = 0; ni < 4; ni++) mma_f16(acc[m0][ni], a0, bh[ni]);
                #pragma unroll
                for (int ni = 0; ni < 4; ni++) mma_f16(acc[m1][ni], a1, bh[ni]);
                #pragma unroll
                for (int ni = 0; ni < 4; ni++) mma_f16(acc[m0][ni], a0, bl[ni]);
                #pragma unroll
                for (int ni = 0; ni < 4; ni++) mma_f16(acc[m1][ni], a1, bl[ni]);
                const uint4 l0 = als[((rbb + m0) * 2 + ks) * 32 + lane];
                const uint4 l1 = als[((rbb + m1) * 2 + ks) * 32 + lane];
                #pragma unroll
                for (int ni = 0; ni < 4; ni++) mma_f16(acc[m0][ni], l0, bh[ni]);
                #pragma unroll
                for (int ni = 0; ni < 4; ni++) mma_f16(acc[m1][ni], l1, bh[ni]);
            }
        }
        __syncthreads();
        if (c + STAGES < NC) stage_load(c + STAGES, st);
        CP_COMMIT();
        st = (st + 1 == STAGES) ? 0 : st + 1;
    }

    // epilogue: unscale 2^-8, spike -> smem tile (stride 132), colsum + fp16 ratep
    constexpr float SC = 1.0f / 256.0f;
    const int   T    = *Tptr;
    const float invT = 1.0f / (float)T;
    __syncthreads();
    #pragma unroll
    for (int ni = 0; ni < 4; ni++) {
        const int cl = wn + ni * 8 + 2 * tq;
        const float be0 = beta[colBase + cl];
        const float be1 = beta[colBase + cl + 1];
        #pragma unroll
        for (int mi = 0; mi < 4; mi++) {
            const int r0 = wm + mi * 16 + gq;
            sm[r0 * 132 + cl]           = spike_rate_of(acc[mi][ni][0] * SC, be0, T, invT);
            sm[r0 * 132 + cl + 1]       = spike_rate_of(acc[mi][ni][1] * SC, be1, T, invT);
            sm[(r0 + 8) * 132 + cl]     = spike_rate_of(acc[mi][ni][2] * SC, be0, T, invT);
            sm[(r0 + 8) * 132 + cl + 1] = spike_rate_of(acc[mi][ni][3] * SC, be1, T, invT);
        }
    }
    __syncthreads();
    if (tid < 128) {
        float s = 0.0f;
        #pragma unroll 8
        for (int r = 0; r < 128; r++) s += sm[r * 132 + tid];
        atomicAdd(&g_colsum[colBase + tid], s);   // exact: multiples of 1/8
    }
    #pragma unroll
    for (int i = 0; i < 8; i++) {
        const int idx = i * 256 + tid;
        const int l2  = idx & 31;
        const int t2  = idx >> 5;
        const int kcj = t2 >> 5;
        const int pos = t2 & 31;
        const int g2 = l2 >> 2, q2 = l2 & 3;
        const int ml = (pos >> 2) * 16;
        const int fl = kcj * 64 + (pos & 3) * 16;
        const int ra = ml + g2, rb2 = ml + g2 + 8;
        const int c0 = fl + 2 * q2, c8 = fl + 2 * q2 + 8;
        uint4 v;
        v.x = pack_h2(sm[ra * 132 + c0],  sm[ra * 132 + c0 + 1]);
        v.y = pack_h2(sm[rb2 * 132 + c0], sm[rb2 * 132 + c0 + 1]);
        v.z = pack_h2(sm[ra * 132 + c8],  sm[ra * 132 + c8 + 1]);
        v.w = pack_h2(sm[rb2 * 132 + c8], sm[rb2 * 132 + c8 + 1]);
        g_ratep[((size_t)(colBase / 64 + kcj) * 32 + mtile) * 1024 + pos * 32 + l2] = v;
    }

    // publish: rate tile globally visible, then bump row counter
    __threadfence();
    __syncthreads();
    if (tid == 0) atomicAdd(&g_rowdone[mtile], 1);
}

// ------------------------------------------------------ GEMM2 tile (R9 body)
__device__ __forceinline__
void gemm2_tile(char* smc, int mtile, int ntile, float* __restrict__ C)
{
    constexpr int TILE = 16384;                  // 128x64 fp16
    constexpr int STAGE = 2 * TILE;
    constexpr int NC = cfg::Ff / 64;             // 64
    constexpr int STAGES = 3;

    const int tid = threadIdx.x, lane = tid & 31, wid = tid >> 5;
    const int gq = lane >> 2, tq = lane & 3;
    const int rowBase = mtile * 128, colBase = ntile * 128;
    const int rbb = (wid & 1) * 4, nbb = (wid >> 1) * 4;
    const int wm = (wid & 1) * 64, wn = (wid >> 1) * 32;
    const uint32_t sb = (uint32_t)__cvta_generic_to_shared(smc);

    const uint4* pA = g_ratep + (size_t)mtile * 1024;
    const uint4* pB = g_dw + (size_t)ntile * 1024;
    constexpr size_t strideA = (size_t)32 * 1024;
    constexpr size_t strideB = (size_t)8 * 1024;

    auto stage_load = [&](int c, int st) {
        const uint32_t d = sb + (uint32_t)st * STAGE;
        const uint4* a = pA + (size_t)c * strideA;
        const uint4* b = pB + (size_t)c * strideB;
        #pragma unroll
        for (int q = 0; q < 4; q++) {
            const int idx = q * 256 + tid;
            cp16(d + idx * 16, a + idx);
            cp16(d + TILE + idx * 16, b + idx);
        }
    };

    float acc[4][4][4];
    #pragma unroll
    for (int mi = 0; mi < 4; mi++)
        #pragma unroll
        for (int ni = 0; ni < 4; ni++)
            #pragma unroll
            for (int q = 0; q < 4; q++) acc[mi][ni][q] = 0.0f;

    #pragma unroll
    for (int s = 0; s < STAGES; s++) { stage_load(s, s); CP_COMMIT(); }

    int st = 0;
    for (int c = 0; c < NC; c++) {
        CP_WAIT2();
        __syncthreads();
        const uint4* ahs = (const uint4*)(smc + st * STAGE);
        const uint2* bhs = (const uint2*)(smc + st * STAGE + TILE);

        #pragma unroll
        for (int ks = 0; ks < 4; ks++) {
            uint2 bh[4];
            #pragma unroll
            for (int ni = 0; ni < 4; ni++)
                bh[ni] = bhs[((nbb + ni) * 4 + ks) * 32 + lane];
            #pragma unroll
            for (int mp = 0; mp < 2; mp++) {
                const int m0 = 2 * mp, m1 = 2 * mp + 1;
                const uint4 a0 = ahs[((rbb + m0) * 4 + ks) * 32 + lane];
                const uint4 a1 = ahs[((rbb + m1) * 4 + ks) * 32 + lane];
                #pragma unroll
                for (int ni = 0; ni < 4; ni++) mma_f16(acc[m0][ni], a0, bh[ni]);
                #pragma unroll
                for (int ni = 0; ni < 4; ni++) mma_f16(acc[m1][ni], a1, bh[ni]);
            }
        }
        __syncthreads();
        if (c + STAGES < NC) stage_load(c + STAGES, st);
        CP_COMMIT();
        st = (st + 1 == STAGES) ? 0 : st + 1;
    }

    constexpr float SC = 1.0f / 16.0f;
    #pragma unroll
    for (int ni = 0; ni < 4; ni++) {
        const int cglob = colBase + wn + ni * 8 + 2 * tq;
        #pragma unroll
        for (int mi = 0; mi < 4; mi++) {
            const int r0 = rowBase + wm + mi * 16 + gq;
            *(float2*)(C + (size_t)r0 * cfg::Dd + cglob) =
                make_float2(acc[mi][ni][0] * SC, acc[mi][ni][1] * SC);
            *(float2*)(C + (size_t)(r0 + 8) * cfg::Dd + cglob) =
                make_float2(acc[mi][ni][2] * SC, acc[mi][ni][3] * SC);
        }
    }
}

// ------------------------------------------- fused persistent work-queue kernel
__global__ __launch_bounds__(256, 2)
void tc_fused(const float* __restrict__ beta, const int* __restrict__ Tptr,
              float* __restrict__ out)
{
    extern __shared__ char smc[];
    __shared__ int s_widx;

    for (;;) {
        __syncthreads();                          // prior tile fully done with smem
        if (threadIdx.x == 0) s_widx = atomicAdd(&g_ctr, 1);
        __syncthreads();
        const int w = s_widx;
        if (w >= 1024 + 256) return;

        if (w < 1024) {
            gemm1_tile(smc, w >> 5, w & 31, beta, Tptr);
        } else {
            const int t = w - 1024;
            const int mt = t >> 3, nt = t & 7;
            if (threadIdx.x == 0) {
                while (atomicAdd(&g_rowdone[mt], 0) < 32) __nanosleep(64);
            }
            __syncthreads();
            __threadfence();                      // acquire: row's ratep visible
            gemm2_tile(smc, mt, nt, out);
        }
    }
}

// -------------------------------------------------------------------- launch
extern "C" void kernel_launch(void* const* d_in, const int* in_sizes, int n_in,
                              void* d_out, int out_size)
{
    const float* x      = (const float*)d_in[0];
    const float* w_up   = (const float*)d_in[1];
    const float* w_down = (const float*)d_in[2];
    const float* beta   = (const float*)d_in[3];
    const int*   Tptr   = (const int*)d_in[4];

    float* out = (float*)d_out;
    float* rpu = out + (size_t)cfg::M * cfg::Dd;

    pack_all<<<10240, 256>>>(x, w_up, w_down);

    constexpr int SMEM = 98304;   // 96 KB: GEMM1 3x32KB == GEMM2 3x(16+16)KB
    cudaFuncSetAttribute(tc_fused, cudaFuncAttributeMaxDynamicSharedMemorySize, SMEM);

    tc_fused<<<296, 256, SMEM>>>(beta, Tptr, out);

    finalize_rpu<<<cfg::Ff / 256, 256>>>(rpu);
}

// round 13
// speedup vs baseline: 1.1323x; 1.0847x over previous
#include <cuda_runtime.h>
#include <cuda_fp16.h>
#include <cstdint>

// SpikingMLP (R9 math, single-barrier pipelines, fused pack):
//   GEMM1 (fp16 m16n8k16 3-pass, w_up*2^8): rate = spike_rate(x @ w_up^T)
//   GEMM2 (fp16 single pass, w_down*2^4):   out  = rate @ w_down^T / 2^4
//   rate_per_unit via exact atomic column sums in GEMM1 epilogue.

namespace cfg {
constexpr int M  = 4096;
constexpr int Dd = 1024;
constexpr int Ff = 4096;
}

__device__ uint4 g_axh[(size_t)32 * 32 * 512];
__device__ uint4 g_axl[(size_t)32 * 32 * 512];
__device__ uint4 g_buh[(size_t)32 * 32 * 512];
__device__ uint4 g_bul[(size_t)32 * 32 * 512];
__device__ uint4 g_dw[(size_t)cfg::Dd * cfg::Ff / 8];    // w_down * 2^4
__device__ uint4 g_ratep[(size_t)cfg::M * cfg::Ff / 8];  // rate fp16, GEMM2-A packed
__device__ float g_colsum[cfg::Ff];

// ------------------------------------------------------------------ helpers
__device__ __forceinline__ uint32_t pack_h2(float a, float b) {
    __half2 p = __floats2half2_rn(a, b);
    return *(uint32_t*)&p;
}
__device__ __forceinline__ void mma_f16(float c[4], const uint4& a, const uint2& b) {
    asm volatile(
        "mma.sync.aligned.m16n8k16.row.col.f32.f16.f16.f32 "
        "{%0,%1,%2,%3}, {%4,%5,%6,%7}, {%8,%9}, {%0,%1,%2,%3};"
        : "+f"(c[0]), "+f"(c[1]), "+f"(c[2]), "+f"(c[3])
        : "r"(a.x), "r"(a.y), "r"(a.z), "r"(a.w), "r"(b.x), "r"(b.y));
}
__device__ __forceinline__ void cp16(uint32_t sdst, const void* gsrc) {
    asm volatile("cp.async.cg.shared.global [%0], [%1], 16;" :: "r"(sdst), "l"(gsrc));
}
#define CP_COMMIT() asm volatile("cp.async.commit_group;" ::: "memory")
#define CP_WAIT1()  asm volatile("cp.async.wait_group 1;" ::: "memory")

__device__ __forceinline__ float spike_rate_of(float h, float be, int T, float invT) {
    float v = 0.0f; int cnt = 0;
    for (int t = 0; t < T; t++) {
        v = be * v + h;
        if (v > 1.0f) { cnt++; v -= 1.0f; }
    }
    return (float)cnt * invT;
}

// ----------------------------------------------------------- fused pack kernel
// blocks [0,2048): pack x | [2048,6144): pack w_up | [6144,10240): pack w_down
__global__ void pack_all(const float* __restrict__ x,
                         const float* __restrict__ w_up,
                         const float* __restrict__ w_down)
{
    const int bid = blockIdx.x;
    const int tid = threadIdx.x;
    if (bid < 16) g_colsum[bid * 256 + tid] = 0.0f;

    const int lane = tid & 31;
    const int gq = lane >> 2, tq = lane & 3;

    if (bid < 2048) {                         // ---- x -> A hi/lo frags
        constexpr int K = 1024, KB = K / 16;
        const int wg  = (bid * 256 + tid) >> 5;
        const int rbg = wg / KB, kbg = wg % KB;
        const float* s = x + (size_t)(rbg * 16) * K + kbg * 16;
        float v[8];
        v[0] = s[(size_t)gq * K + 2 * tq];       v[1] = s[(size_t)gq * K + 2 * tq + 1];
        v[2] = s[(size_t)(gq + 8) * K + 2 * tq]; v[3] = s[(size_t)(gq + 8) * K + 2 * tq + 1];
        v[4] = s[(size_t)gq * K + 2 * tq + 8];   v[5] = s[(size_t)gq * K + 2 * tq + 9];
        v[6] = s[(size_t)(gq + 8) * K + 2 * tq + 8]; v[7] = s[(size_t)(gq + 8) * K + 2 * tq + 9];
        float h[8], l[8];
        #pragma unroll
        for (int i = 0; i < 8; i++) {
            h[i] = __half2float(__float2half_rn(v[i]));
            l[i] = v[i] - h[i];
        }
        const int mtile = rbg >> 3, rb = rbg & 7, kc = kbg >> 1, kb = kbg & 1;
        const size_t idx = (((size_t)kc * 32 + mtile) * 16 + rb * 2 + kb) * 32 + lane;
        g_axh[idx] = make_uint4(pack_h2(h[0], h[1]), pack_h2(h[2], h[3]),
                                pack_h2(h[4], h[5]), pack_h2(h[6], h[7]));
        g_axl[idx] = make_uint4(pack_h2(l[0], l[1]), pack_h2(l[2], l[3]),
                                pack_h2(l[4], l[5]), pack_h2(l[6], l[7]));
    } else if (bid < 6144) {                  // ---- w_up * 2^8 -> B hi/lo frags
        constexpr int K = 1024, KB = K / 16;
        const int wg  = ((bid - 2048) * 256 + tid) >> 5;
        const int nbg = wg / KB, kbg = wg % KB;
        const float* s = w_up + (size_t)(nbg * 8 + gq) * K + kbg * 16;
        const float v0 = s[2 * tq] * 256.0f,     v1 = s[2 * tq + 1] * 256.0f;
        const float v2 = s[2 * tq + 8] * 256.0f, v3 = s[2 * tq + 9] * 256.0f;
        const float h0 = __half2float(__float2half_rn(v0));
        const float h1 = __half2float(__float2half_rn(v1));
        const float h2 = __half2float(__float2half_rn(v2));
        const float h3 = __half2float(__float2half_rn(v3));
        const int ntile = nbg >> 4, nb = nbg & 15, kc = kbg >> 1, kb = kbg & 1;
        const size_t idx = ((((size_t)kc * 32 + ntile) * 16 + nb) * 2 + kb) * 32 + lane;
        ((uint2*)g_buh)[idx] = make_uint2(pack_h2(h0, h1), pack_h2(h2, h3));
        ((uint2*)g_bul)[idx] = make_uint2(pack_h2(v0 - h0, v1 - h1), pack_h2(v2 - h2, v3 - h3));
    } else {                                  // ---- w_down * 2^4 -> fp16 frags
        constexpr int K = 4096, KB16 = K / 16;
        const int wg  = ((bid - 6144) * 256 + tid) >> 5;
        const int nbg = wg / KB16, kbg = wg % KB16;
        const float* s = w_down + (size_t)(nbg * 8 + gq) * K + kbg * 16;
        const float v0 = s[2 * tq] * 16.0f,     v1 = s[2 * tq + 1] * 16.0f;
        const float v2 = s[2 * tq + 8] * 16.0f, v3 = s[2 * tq + 9] * 16.0f;
        const int ntile = nbg >> 4, nb = nbg & 15, kc = kbg >> 2, kb = kbg & 3;
        const size_t idx = ((((size_t)kc * 8 + ntile) * 16 + nb) * 4 + kb) * 32 + lane;
        ((uint2*)g_dw)[idx] = make_uint2(pack_h2(v0, v1), pack_h2(v2, v3));
    }
}

__global__ void finalize_rpu(float* __restrict__ rpu) {
    const int f = blockIdx.x * 256 + threadIdx.x;
    rpu[f] = g_colsum[f] * (1.0f / (float)cfg::M);   // exact
}

// --------------------------------------------------- GEMM1 (fp16, 3 passes)
// single-barrier pipeline: per chunk: wait(1); sync; load c+2 -> stage (c-1)%3; consume c%3
__global__ __launch_bounds__(256, 2)
void tc_gemm1(const float* __restrict__ beta, const int* __restrict__ Tptr)
{
    constexpr int TILE  = 8192;                  // 128x32 fp16
    constexpr int STAGE = 4 * TILE;              // Ah, Al, Bh, Bl
    constexpr int NC    = cfg::Dd / 32;          // 32
    extern __shared__ char smc[];
    float* sm = (float*)smc;

    const int tid = threadIdx.x, lane = tid & 31, wid = tid >> 5;
    const int gq = lane >> 2, tq = lane & 3;
    const int mtile = blockIdx.y, ntile = blockIdx.x;
    const int colBase = ntile * 128;
    const int rbb = (wid & 1) * 4, nbb = (wid >> 1) * 4;
    const int wm = (wid & 1) * 64, wn = (wid >> 1) * 32;
    const uint32_t sb = (uint32_t)__cvta_generic_to_shared(smc);

    const uint4* pAh = g_axh + (size_t)mtile * 512;
    const uint4* pAl = g_axl + (size_t)mtile * 512;
    const uint4* pBh = g_buh + (size_t)ntile * 512;
    const uint4* pBl = g_bul + (size_t)ntile * 512;
    constexpr size_t strideKC = (size_t)32 * 512;

    auto stage_load = [&](int c, int st) {
        const uint32_t d = sb + (uint32_t)st * STAGE;
        const size_t o = (size_t)c * strideKC;
        #pragma unroll
        for (int q = 0; q < 2; q++) {
            const int idx = q * 256 + tid;
            cp16(d + idx * 16,            pAh + o + idx);
            cp16(d + TILE + idx * 16,     pAl + o + idx);
            cp16(d + 2 * TILE + idx * 16, pBh + o + idx);
            cp16(d + 3 * TILE + idx * 16, pBl + o + idx);
        }
    };

    float acc[4][4][4];
    #pragma unroll
    for (int mi = 0; mi < 4; mi++)
        #pragma unroll
        for (int ni = 0; ni < 4; ni++)
            #pragma unroll
            for (int q = 0; q < 4; q++) acc[mi][ni][q] = 0.0f;

    stage_load(0, 0); CP_COMMIT();
    stage_load(1, 1); CP_COMMIT();

    for (int c = 0; c < NC; c++) {
        CP_WAIT1();
        __syncthreads();                         // all warps done with chunk c-1
        if (c + 2 < NC) stage_load(c + 2, (c + 2) % 3);   // (c+2)%3 == (c-1)%3
        CP_COMMIT();

        const char* s0  = smc + (c % 3) * STAGE;
        const uint4* ahs = (const uint4*)(s0);
        const uint4* als = (const uint4*)(s0 + TILE);
        const uint2* bhs = (const uint2*)(s0 + 2 * TILE);
        const uint2* bls = (const uint2*)(s0 + 3 * TILE);

        #pragma unroll
        for (int ks = 0; ks < 2; ks++) {
            uint2 bh[4], bl[4];
            #pragma unroll
            for (int ni = 0; ni < 4; ni++) {
                bh[ni] = bhs[((nbb + ni) * 2 + ks) * 32 + lane];
                bl[ni] = bls[((nbb + ni) * 2 + ks) * 32 + lane];
            }
            #pragma unroll
            for (int mp = 0; mp < 2; mp++) {
                const int m0 = 2 * mp, m1 = 2 * mp + 1;
                const uint4 a0 = ahs[((rbb + m0) * 2 + ks) * 32 + lane];
                const uint4 a1 = ahs[((rbb + m1) * 2 + ks) * 32 + lane];
                #pragma unroll
                for (int ni = 0; ni < 4; ni++) mma_f16(acc[m0][ni], a0, bh[ni]);
                #pragma unroll
                for (int ni = 0; ni < 4; ni++) mma_f16(acc[m1][ni], a1, bh[ni]);
                #pragma unroll
                for (int ni = 0; ni < 4; ni++) mma_f16(acc[m0][ni], a0, bl[ni]);
                #pragma unroll
                for (int ni = 0; ni < 4; ni++) mma_f16(acc[m1][ni], a1, bl[ni]);
                const uint4 l0 = als[((rbb + m0) * 2 + ks) * 32 + lane];
                const uint4 l1 = als[((rbb + m1) * 2 + ks) * 32 + lane];
                #pragma unroll
                for (int ni = 0; ni < 4; ni++) mma_f16(acc[m0][ni], l0, bh[ni]);
                #pragma unroll
                for (int ni = 0; ni < 4; ni++) mma_f16(acc[m1][ni], l1, bh[ni]);
            }
        }
    }

    // epilogue: unscale 2^-8, spike -> smem tile (stride 132), colsum + fp16 ratep
    constexpr float SC = 1.0f / 256.0f;
    const int   T    = *Tptr;
    const float invT = 1.0f / (float)T;
    __syncthreads();
    #pragma unroll
    for (int ni = 0; ni < 4; ni++) {
        const int cl = wn + ni * 8 + 2 * tq;
        const float be0 = beta[colBase + cl];
        const float be1 = beta[colBase + cl + 1];
        #pragma unroll
        for (int mi = 0; mi < 4; mi++) {
            const int r0 = wm + mi * 16 + gq;
            sm[r0 * 132 + cl]           = spike_rate_of(acc[mi][ni][0] * SC, be0, T, invT);
            sm[r0 * 132 + cl + 1]       = spike_rate_of(acc[mi][ni][1] * SC, be1, T, invT);
            sm[(r0 + 8) * 132 + cl]     = spike_rate_of(acc[mi][ni][2] * SC, be0, T, invT);
            sm[(r0 + 8) * 132 + cl + 1] = spike_rate_of(acc[mi][ni][3] * SC, be1, T, invT);
        }
    }
    __syncthreads();
    if (tid < 128) {
        float s = 0.0f;
        #pragma unroll 8
        for (int r = 0; r < 128; r++) s += sm[r * 132 + tid];
        atomicAdd(&g_colsum[colBase + tid], s);   // exact: multiples of 1/8
    }
    #pragma unroll
    for (int i = 0; i < 8; i++) {
        const int idx = i * 256 + tid;
        const int l2  = idx & 31;
        const int t2  = idx >> 5;
        const int kcj = t2 >> 5;
        const int pos = t2 & 31;
        const int g2 = l2 >> 2, q2 = l2 & 3;
        const int ml = (pos >> 2) * 16;
        const int fl = kcj * 64 + (pos & 3) * 16;
        const int ra = ml + g2, rb2 = ml + g2 + 8;
        const int c0 = fl + 2 * q2, c8 = fl + 2 * q2 + 8;
        uint4 v;
        v.x = pack_h2(sm[ra * 132 + c0],  sm[ra * 132 + c0 + 1]);
        v.y = pack_h2(sm[rb2 * 132 + c0], sm[rb2 * 132 + c0 + 1]);
        v.z = pack_h2(sm[ra * 132 + c8],  sm[ra * 132 + c8 + 1]);
        v.w = pack_h2(sm[rb2 * 132 + c8], sm[rb2 * 132 + c8 + 1]);
        g_ratep[((size_t)(colBase / 64 + kcj) * 32 + mtile) * 1024 + pos * 32 + l2] = v;
    }
}

// --------------------------------------------- GEMM2 (fp16, single pass)
__global__ __launch_bounds__(256, 2)
void tc_gemm2(const uint4* __restrict__ A, const uint4* __restrict__ B,
              float* __restrict__ C)
{
    constexpr int TILE = 16384;                  // 128x64 fp16
    constexpr int STAGE = 2 * TILE;
    constexpr int NC = cfg::Ff / 64;             // 64
    extern __shared__ char smc[];

    const int tid = threadIdx.x, lane = tid & 31, wid = tid >> 5;
    const int gq = lane >> 2, tq = lane & 3;
    const int mtile = blockIdx.y, ntile = blockIdx.x;
    const int rowBase = mtile * 128, colBase = ntile * 128;
    const int rbb = (wid & 1) * 4, nbb = (wid >> 1) * 4;
    const int wm = (wid & 1) * 64, wn = (wid >> 1) * 32;
    const uint32_t sb = (uint32_t)__cvta_generic_to_shared(smc);

    const uint4* pA = A + (size_t)mtile * 1024;
    const uint4* pB = B + (size_t)ntile * 1024;
    constexpr size_t strideA = (size_t)32 * 1024;
    constexpr size_t strideB = (size_t)8 * 1024;

    auto stage_load = [&](int c, int st) {
        const uint32_t d = sb + (uint32_t)st * STAGE;
        const uint4* a = pA + (size_t)c * strideA;
        const uint4* b = pB + (size_t)c * strideB;
        #pragma unroll
        for (int q = 0; q < 4; q++) {
            const int idx = q * 256 + tid;
            cp16(d + idx * 16, a + idx);
            cp16(d + TILE + idx * 16, b + idx);
        }
    };

    float acc[4][4][4];
    #pragma unroll
    for (int mi = 0; mi < 4; mi++)
        #pragma unroll
        for (int ni = 0; ni < 4; ni++)
            #pragma unroll
            for (int q = 0; q < 4; q++) acc[mi][ni][q] = 0.0f;

    stage_load(0, 0); CP_COMMIT();
    stage_load(1, 1); CP_COMMIT();

    for (int c = 0; c < NC; c++) {
        CP_WAIT1();
        __syncthreads();
        if (c + 2 < NC) stage_load(c + 2, (c + 2) % 3);
        CP_COMMIT();

        const char* s0  = smc + (c % 3) * STAGE;
        const uint4* ahs = (const uint4*)(s0);
        const uint2* bhs = (const uint2*)(s0 + TILE);

        #pragma unroll
        for (int ks = 0; ks < 4; ks++) {
            uint2 bh[4];
            #pragma unroll
            for (int ni = 0; ni < 4; ni++)
                bh[ni] = bhs[((nbb + ni) * 4 + ks) * 32 + lane];
            #pragma unroll
            for (int mp = 0; mp < 2; mp++) {
                const int m0 = 2 * mp, m1 = 2 * mp + 1;
                const uint4 a0 = ahs[((rbb + m0) * 4 + ks) * 32 + lane];
                const uint4 a1 = ahs[((rbb + m1) * 4 + ks) * 32 + lane];
                #pragma unroll
                for (int ni = 0; ni < 4; ni++) mma_f16(acc[m0][ni], a0, bh[ni]);
                #pragma unroll
                for (int ni = 0; ni < 4; ni++) mma_f16(acc[m1][ni], a1, bh[ni]);
            }
        }
    }

    constexpr float SC = 1.0f / 16.0f;           // exact unscale of w_down*16
    #pragma unroll
    for (int ni = 0; ni < 4; ni++) {
        const int cglob = colBase + wn + ni * 8 + 2 * tq;
        #pragma unroll
        for (int mi = 0; mi < 4; mi++) {
            const int r0 = rowBase + wm + mi * 16 + gq;
            *(float2*)(C + (size_t)r0 * cfg::Dd + cglob) =
                make_float2(acc[mi][ni][0] * SC, acc[mi][ni][1] * SC);
            *(float2*)(C + (size_t)(r0 + 8) * cfg::Dd + cglob) =
                make_float2(acc[mi][ni][2] * SC, acc[mi][ni][3] * SC);
        }
    }
}

// -------------------------------------------------------------------- launch
extern "C" void kernel_launch(void* const* d_in, const int* in_sizes, int n_in,
                              void* d_out, int out_size)
{
    const float* x      = (const float*)d_in[0];
    const float* w_up   = (const float*)d_in[1];
    const float* w_down = (const float*)d_in[2];
    const float* beta   = (const float*)d_in[3];
    const int*   Tptr   = (const int*)d_in[4];

    float* out = (float*)d_out;
    float* rpu = out + (size_t)cfg::M * cfg::Dd;

    uint4 *dw, *ratep;
    cudaGetSymbolAddress((void**)&dw, g_dw);
    cudaGetSymbolAddress((void**)&ratep, g_ratep);

    pack_all<<<10240, 256>>>(x, w_up, w_down);

    constexpr int SMEM1 = 3 * 4 * 8192;    // 98304 B
    constexpr int SMEM2 = 3 * 2 * 16384;   // 98304 B
    cudaFuncSetAttribute(tc_gemm1, cudaFuncAttributeMaxDynamicSharedMemorySize, SMEM1);
    cudaFuncSetAttribute(tc_gemm2, cudaFuncAttributeMaxDynamicSharedMemorySize, SMEM2);

    tc_gemm1<<<dim3(cfg::Ff / 128, cfg::M / 128), 256, SMEM1>>>(beta, Tptr);

    finalize_rpu<<<cfg::Ff / 256, 256>>>(rpu);

    tc_gemm2<<<dim3(cfg::Dd / 128, cfg::M / 128), 256, SMEM2>>>(ratep, dw, out);
}

// round 14
// speedup vs baseline: 1.2594x; 1.1122x over previous
#include <cuda_runtime.h>
#include <cuda_fp16.h>
#include <cstdint>

// SpikingMLP (R9 GEMM bodies + fused pack + rpu folded into GEMM2):
//   GEMM1 (fp16 m16n8k16 3-pass, w_up*2^8): rate = spike_rate(x @ w_up^T)
//   GEMM2 (fp16 single pass, w_down*2^4):   out  = rate @ w_down^T / 2^4
//   rate_per_unit via exact atomic column sums in GEMM1 epilogue; written by GEMM2 CTA(0,0).

namespace cfg {
constexpr int M  = 4096;
constexpr int Dd = 1024;
constexpr int Ff = 4096;
}

__device__ uint4 g_axh[(size_t)32 * 32 * 512];
__device__ uint4 g_axl[(size_t)32 * 32 * 512];
__device__ uint4 g_buh[(size_t)32 * 32 * 512];
__device__ uint4 g_bul[(size_t)32 * 32 * 512];
__device__ uint4 g_dw[(size_t)cfg::Dd * cfg::Ff / 8];    // w_down * 2^4
__device__ uint4 g_ratep[(size_t)cfg::M * cfg::Ff / 8];  // rate fp16, GEMM2-A packed
__device__ float g_colsum[cfg::Ff];

// ------------------------------------------------------------------ helpers
__device__ __forceinline__ uint32_t pack_h2(float a, float b) {
    __half2 p = __floats2half2_rn(a, b);       // .x = a (low half)
    return *(uint32_t*)&p;
}
__device__ __forceinline__ void mma_f16(float c[4], const uint4& a, const uint2& b) {
    asm volatile(
        "mma.sync.aligned.m16n8k16.row.col.f32.f16.f16.f32 "
        "{%0,%1,%2,%3}, {%4,%5,%6,%7}, {%8,%9}, {%0,%1,%2,%3};"
        : "+f"(c[0]), "+f"(c[1]), "+f"(c[2]), "+f"(c[3])
        : "r"(a.x), "r"(a.y), "r"(a.z), "r"(a.w), "r"(b.x), "r"(b.y));
}
__device__ __forceinline__ void cp16(uint32_t sdst, const void* gsrc) {
    asm volatile("cp.async.cg.shared.global [%0], [%1], 16;" :: "r"(sdst), "l"(gsrc));
}
#define CP_COMMIT() asm volatile("cp.async.commit_group;" ::: "memory")
#define CP_WAIT2()  asm volatile("cp.async.wait_group 2;" ::: "memory")

__device__ __forceinline__ float spike_rate_of(float h, float be, int T, float invT) {
    float v = 0.0f; int cnt = 0;
    for (int t = 0; t < T; t++) {
        v = be * v + h;
        if (v > 1.0f) { cnt++; v -= 1.0f; }
    }
    return (float)cnt * invT;
}

// ----------------------------------------------------------- fused pack kernel
// blocks [0,2048): pack x | [2048,6144): pack w_up | [6144,10240): pack w_down
__global__ void pack_all(const float* __restrict__ x,
                         const float* __restrict__ w_up,
                         const float* __restrict__ w_down)
{
    const int bid = blockIdx.x;
    const int tid = threadIdx.x;
    if (bid < 16) g_colsum[bid * 256 + tid] = 0.0f;

    const int lane = tid & 31;
    const int gq = lane >> 2, tq = lane & 3;

    if (bid < 2048) {                         // ---- x -> A hi/lo frags
        constexpr int K = 1024, KB = K / 16;
        const int wg  = (bid * 256 + tid) >> 5;
        const int rbg = wg / KB, kbg = wg % KB;
        const float* s = x + (size_t)(rbg * 16) * K + kbg * 16;
        float v[8];
        v[0] = s[(size_t)gq * K + 2 * tq];       v[1] = s[(size_t)gq * K + 2 * tq + 1];
        v[2] = s[(size_t)(gq + 8) * K + 2 * tq]; v[3] = s[(size_t)(gq + 8) * K + 2 * tq + 1];
        v[4] = s[(size_t)gq * K + 2 * tq + 8];   v[5] = s[(size_t)gq * K + 2 * tq + 9];
        v[6] = s[(size_t)(gq + 8) * K + 2 * tq + 8]; v[7] = s[(size_t)(gq + 8) * K + 2 * tq + 9];
        float h[8], l[8];
        #pragma unroll
        for (int i = 0; i < 8; i++) {
            h[i] = __half2float(__float2half_rn(v[i]));
            l[i] = v[i] - h[i];
        }
        const int mtile = rbg >> 3, rb = rbg & 7, kc = kbg >> 1, kb = kbg & 1;
        const size_t idx = (((size_t)kc * 32 + mtile) * 16 + rb * 2 + kb) * 32 + lane;
        g_axh[idx] = make_uint4(pack_h2(h[0], h[1]), pack_h2(h[2], h[3]),
                                pack_h2(h[4], h[5]), pack_h2(h[6], h[7]));
        g_axl[idx] = make_uint4(pack_h2(l[0], l[1]), pack_h2(l[2], l[3]),
                                pack_h2(l[4], l[5]), pack_h2(l[6], l[7]));
    } else if (bid < 6144) {                  // ---- w_up * 2^8 -> B hi/lo frags
        constexpr int K = 1024, KB = K / 16;
        const int wg  = ((bid - 2048) * 256 + tid) >> 5;
        const int nbg = wg / KB, kbg = wg % KB;
        const float* s = w_up + (size_t)(nbg * 8 + gq) * K + kbg * 16;
        const float v0 = s[2 * tq] * 256.0f,     v1 = s[2 * tq + 1] * 256.0f;
        const float v2 = s[2 * tq + 8] * 256.0f, v3 = s[2 * tq + 9] * 256.0f;
        const float h0 = __half2float(__float2half_rn(v0));
        const float h1 = __half2float(__float2half_rn(v1));
        const float h2 = __half2float(__float2half_rn(v2));
        const float h3 = __half2float(__float2half_rn(v3));
        const int ntile = nbg >> 4, nb = nbg & 15, kc = kbg >> 1, kb = kbg & 1;
        const size_t idx = ((((size_t)kc * 32 + ntile) * 16 + nb) * 2 + kb) * 32 + lane;
        ((uint2*)g_buh)[idx] = make_uint2(pack_h2(h0, h1), pack_h2(h2, h3));
        ((uint2*)g_bul)[idx] = make_uint2(pack_h2(v0 - h0, v1 - h1), pack_h2(v2 - h2, v3 - h3));
    } else {                                  // ---- w_down * 2^4 -> fp16 frags
        constexpr int K = 4096, KB16 = K / 16;
        const int wg  = ((bid - 6144) * 256 + tid) >> 5;
        const int nbg = wg / KB16, kbg = wg % KB16;
        const float* s = w_down + (size_t)(nbg * 8 + gq) * K + kbg * 16;
        const float v0 = s[2 * tq] * 16.0f,     v1 = s[2 * tq + 1] * 16.0f;
        const float v2 = s[2 * tq + 8] * 16.0f, v3 = s[2 * tq + 9] * 16.0f;
        const int ntile = nbg >> 4, nb = nbg & 15, kc = kbg >> 2, kb = kbg & 3;
        const size_t idx = ((((size_t)kc * 8 + ntile) * 16 + nb) * 4 + kb) * 32 + lane;
        ((uint2*)g_dw)[idx] = make_uint2(pack_h2(v0, v1), pack_h2(v2, v3));
    }
}

// --------------------------------------------------- GEMM1 (fp16, 3 passes; R9 body)
__global__ __launch_bounds__(256, 2)
void tc_gemm1(const float* __restrict__ beta, const int* __restrict__ Tptr)
{
    constexpr int TILE  = 8192;                  // 128x32 fp16
    constexpr int STAGE = 4 * TILE;              // Ah, Al, Bh, Bl
    constexpr int NC    = cfg::Dd / 32;          // 32
    constexpr int STAGES = 3;
    extern __shared__ char smc[];
    float* sm = (float*)smc;

    const int tid = threadIdx.x, lane = tid & 31, wid = tid >> 5;
    const int gq = lane >> 2, tq = lane & 3;
    const int mtile = blockIdx.y, ntile = blockIdx.x;
    const int colBase = ntile * 128;
    const int rbb = (wid & 1) * 4, nbb = (wid >> 1) * 4;
    const int wm = (wid & 1) * 64, wn = (wid >> 1) * 32;
    const uint32_t sb = (uint32_t)__cvta_generic_to_shared(smc);

    const uint4* pAh = g_axh + (size_t)mtile * 512;
    const uint4* pAl = g_axl + (size_t)mtile * 512;
    const uint4* pBh = g_buh + (size_t)ntile * 512;
    const uint4* pBl = g_bul + (size_t)ntile * 512;
    constexpr size_t strideKC = (size_t)32 * 512;

    auto stage_load = [&](int c, int st) {
        const uint32_t d = sb + (uint32_t)st * STAGE;
        const size_t o = (size_t)c * strideKC;
        #pragma unroll
        for (int q = 0; q < 2; q++) {
            const int idx = q * 256 + tid;
            cp16(d + idx * 16,            pAh + o + idx);
            cp16(d + TILE + idx * 16,     pAl + o + idx);
            cp16(d + 2 * TILE + idx * 16, pBh + o + idx);
            cp16(d + 3 * TILE + idx * 16, pBl + o + idx);
        }
    };

    float acc[4][4][4];
    #pragma unroll
    for (int mi = 0; mi < 4; mi++)
        #pragma unroll
        for (int ni = 0; ni < 4; ni++)
            #pragma unroll
            for (int q = 0; q < 4; q++) acc[mi][ni][q] = 0.0f;

    #pragma unroll
    for (int s = 0; s < STAGES; s++) { stage_load(s, s); CP_COMMIT(); }

    int st = 0;
    for (int c = 0; c < NC; c++) {
        CP_WAIT2();
        __syncthreads();
        const uint4* ahs = (const uint4*)(smc + st * STAGE);
        const uint4* als = (const uint4*)(smc + st * STAGE + TILE);
        const uint2* bhs = (const uint2*)(smc + st * STAGE + 2 * TILE);
        const uint2* bls = (const uint2*)(smc + st * STAGE + 3 * TILE);

        #pragma unroll
        for (int ks = 0; ks < 2; ks++) {
            uint2 bh[4], bl[4];
            #pragma unroll
            for (int ni = 0; ni < 4; ni++) {
                bh[ni] = bhs[((nbb + ni) * 2 + ks) * 32 + lane];
                bl[ni] = bls[((nbb + ni) * 2 + ks) * 32 + lane];
            }
            #pragma unroll
            for (int mp = 0; mp < 2; mp++) {
                const int m0 = 2 * mp, m1 = 2 * mp + 1;
                const uint4 a0 = ahs[((rbb + m0) * 2 + ks) * 32 + lane];
                const uint4 a1 = ahs[((rbb + m1) * 2 + ks) * 32 + lane];
                #pragma unroll
                for (int ni = 0; ni < 4; ni++) mma_f16(acc[m0][ni], a0, bh[ni]);
                #pragma unroll
                for (int ni = 0; ni < 4; ni++) mma_f16(acc[m1][ni], a1, bh[ni]);
                #pragma unroll
                for (int ni = 0; ni < 4; ni++) mma_f16(acc[m0][ni], a0, bl[ni]);
                #pragma unroll
                for (int ni = 0; ni < 4; ni++) mma_f16(acc[m1][ni], a1, bl[ni]);
                const uint4 l0 = als[((rbb + m0) * 2 + ks) * 32 + lane];
                const uint4 l1 = als[((rbb + m1) * 2 + ks) * 32 + lane];
                #pragma unroll
                for (int ni = 0; ni < 4; ni++) mma_f16(acc[m0][ni], l0, bh[ni]);
                #pragma unroll
                for (int ni = 0; ni < 4; ni++) mma_f16(acc[m1][ni], l1, bh[ni]);
            }
        }
        __syncthreads();
        if (c + STAGES < NC) stage_load(c + STAGES, st);
        CP_COMMIT();
        st = (st + 1 == STAGES) ? 0 : st + 1;
    }

    // epilogue: unscale 2^-8, spike -> smem tile (stride 132), colsum + fp16 ratep
    constexpr float SC = 1.0f / 256.0f;
    const int   T    = *Tptr;
    const float invT = 1.0f / (float)T;
    __syncthreads();
    #pragma unroll
    for (int ni = 0; ni < 4; ni++) {
        const int cl = wn + ni * 8 + 2 * tq;
        const float be0 = beta[colBase + cl];
        const float be1 = beta[colBase + cl + 1];
        #pragma unroll
        for (int mi = 0; mi < 4; mi++) {
            const int r0 = wm + mi * 16 + gq;
            sm[r0 * 132 + cl]           = spike_rate_of(acc[mi][ni][0] * SC, be0, T, invT);
            sm[r0 * 132 + cl + 1]       = spike_rate_of(acc[mi][ni][1] * SC, be1, T, invT);
            sm[(r0 + 8) * 132 + cl]     = spike_rate_of(acc[mi][ni][2] * SC, be0, T, invT);
            sm[(r0 + 8) * 132 + cl + 1] = spike_rate_of(acc[mi][ni][3] * SC, be1, T, invT);
        }
    }
    __syncthreads();
    if (tid < 128) {
        float s = 0.0f;
        #pragma unroll 8
        for (int r = 0; r < 128; r++) s += sm[r * 132 + tid];
        atomicAdd(&g_colsum[colBase + tid], s);   // exact: multiples of 1/8
    }
    #pragma unroll
    for (int i = 0; i < 8; i++) {
        const int idx = i * 256 + tid;
        const int l2  = idx & 31;
        const int t2  = idx >> 5;
        const int kcj = t2 >> 5;
        const int pos = t2 & 31;
        const int g2 = l2 >> 2, q2 = l2 & 3;
        const int ml = (pos >> 2) * 16;
        const int fl = kcj * 64 + (pos & 3) * 16;
        const int ra = ml + g2, rb2 = ml + g2 + 8;
        const int c0 = fl + 2 * q2, c8 = fl + 2 * q2 + 8;
        uint4 v;
        v.x = pack_h2(sm[ra * 132 + c0],  sm[ra * 132 + c0 + 1]);
        v.y = pack_h2(sm[rb2 * 132 + c0], sm[rb2 * 132 + c0 + 1]);
        v.z = pack_h2(sm[ra * 132 + c8],  sm[ra * 132 + c8 + 1]);
        v.w = pack_h2(sm[rb2 * 132 + c8], sm[rb2 * 132 + c8 + 1]);
        g_ratep[((size_t)(colBase / 64 + kcj) * 32 + mtile) * 1024 + pos * 32 + l2] = v;
    }
}

// --------------------------------------------- GEMM2 (fp16, single pass; R9 body)
// Also writes rate_per_unit from CTA (0,0) — colsum is complete when GEMM2 starts.
__global__ __launch_bounds__(256, 2)
void tc_gemm2(const uint4* __restrict__ A, const uint4* __restrict__ B,
              float* __restrict__ C, float* __restrict__ rpu)
{
    constexpr int TILE = 16384;                  // 128x64 fp16
    constexpr int STAGE = 2 * TILE;              // A + B
    constexpr int NC = cfg::Ff / 64;             // 64
    constexpr int STAGES = 3;
    extern __shared__ char smc[];

    const int tid = threadIdx.x, lane = tid & 31, wid = tid >> 5;
    const int gq = lane >> 2, tq = lane & 3;
    const int mtile = blockIdx.y, ntile = blockIdx.x;
    const int rowBase = mtile * 128, colBase = ntile * 128;
    const int rbb = (wid & 1) * 4, nbb = (wid >> 1) * 4;
    const int wm = (wid & 1) * 64, wn = (wid >> 1) * 32;
    const uint32_t sb = (uint32_t)__cvta_generic_to_shared(smc);

    if (mtile == 0 && ntile == 0) {              // fused rate_per_unit
        #pragma unroll
        for (int i = 0; i < 16; i++)
            rpu[i * 256 + tid] = g_colsum[i * 256 + tid] * (1.0f / (float)cfg::M);
    }

    const uint4* pA = A + (size_t)mtile * 1024;
    const uint4* pB = B + (size_t)ntile * 1024;
    constexpr size_t strideA = (size_t)32 * 1024;
    constexpr size_t strideB = (size_t)8 * 1024;

    auto stage_load = [&](int c, int st) {
        const uint32_t d = sb + (uint32_t)st * STAGE;
        const uint4* a = pA + (size_t)c * strideA;
        const uint4* b = pB + (size_t)c * strideB;
        #pragma unroll
        for (int q = 0; q < 4; q++) {
            const int idx = q * 256 + tid;
            cp16(d + idx * 16, a + idx);
            cp16(d + TILE + idx * 16, b + idx);
        }
    };

    float acc[4][4][4];
    #pragma unroll
    for (int mi = 0; mi < 4; mi++)
        #pragma unroll
        for (int ni = 0; ni < 4; ni++)
            #pragma unroll
            for (int q = 0; q < 4; q++) acc[mi][ni][q] = 0.0f;

    #pragma unroll
    for (int s = 0; s < STAGES; s++) { stage_load(s, s); CP_COMMIT(); }

    int st = 0;
    for (int c = 0; c < NC; c++) {
        CP_WAIT2();
        __syncthreads();
        const uint4* ahs = (const uint4*)(smc + st * STAGE);
        const uint2* bhs = (const uint2*)(smc + st * STAGE + TILE);

        #pragma unroll
        for (int ks = 0; ks < 4; ks++) {
            uint2 bh[4];
            #pragma unroll
            for (int ni = 0; ni < 4; ni++)
                bh[ni] = bhs[((nbb + ni) * 4 + ks) * 32 + lane];
            #pragma unroll
            for (int mp = 0; mp < 2; mp++) {
                const int m0 = 2 * mp, m1 = 2 * mp + 1;
                const uint4 a0 = ahs[((rbb + m0) * 4 + ks) * 32 + lane];
                const uint4 a1 = ahs[((rbb + m1) * 4 + ks) * 32 + lane];
                #pragma unroll
                for (int ni = 0; ni < 4; ni++) mma_f16(acc[m0][ni], a0, bh[ni]);
                #pragma unroll
                for (int ni = 0; ni < 4; ni++) mma_f16(acc[m1][ni], a1, bh[ni]);
            }
        }
        __syncthreads();
        if (c + STAGES < NC) stage_load(c + STAGES, st);
        CP_COMMIT();
        st = (st + 1 == STAGES) ? 0 : st + 1;
    }

    constexpr float SC = 1.0f / 16.0f;           // exact unscale of w_down*16
    #pragma unroll
    for (int ni = 0; ni < 4; ni++) {
        const int cglob = colBase + wn + ni * 8 + 2 * tq;
        #pragma unroll
        for (int mi = 0; mi < 4; mi++) {
            const int r0 = rowBase + wm + mi * 16 + gq;
            *(float2*)(C + (size_t)r0 * cfg::Dd + cglob) =
                make_float2(acc[mi][ni][0] * SC, acc[mi][ni][1] * SC);
            *(float2*)(C + (size_t)(r0 + 8) * cfg::Dd + cglob) =
                make_float2(acc[mi][ni][2] * SC, acc[mi][ni][3] * SC);
        }
    }
}

// -------------------------------------------------------------------- launch
extern "C" void kernel_launch(void* const* d_in, const int* in_sizes, int n_in,
                              void* d_out, int out_size)
{
    const float* x      = (const float*)d_in[0];
    const float* w_up   = (const float*)d_in[1];
    const float* w_down = (const float*)d_in[2];
    const float* beta   = (const float*)d_in[3];
    const int*   Tptr   = (const int*)d_in[4];

    float* out = (float*)d_out;
    float* rpu = out + (size_t)cfg::M * cfg::Dd;

    uint4 *dw, *ratep;
    cudaGetSymbolAddress((void**)&dw, g_dw);
    cudaGetSymbolAddress((void**)&ratep, g_ratep);

    pack_all<<<10240, 256>>>(x, w_up, w_down);

    constexpr int SMEM1 = 3 * 4 * 8192;    // 98304 B
    constexpr int SMEM2 = 3 * 2 * 16384;   // 98304 B
    cudaFuncSetAttribute(tc_gemm1, cudaFuncAttributeMaxDynamicSharedMemorySize, SMEM1);
    cudaFuncSetAttribute(tc_gemm2, cudaFuncAttributeMaxDynamicSharedMemorySize, SMEM2);

    tc_gemm1<<<dim3(cfg::Ff / 128, cfg::M / 128), 256, SMEM1>>>(beta, Tptr);

    tc_gemm2<<<dim3(cfg::Dd / 128, cfg::M / 128), 256, SMEM2>>>(ratep, dw, out, rpu);
}

// round 15
// speedup vs baseline: 1.2848x; 1.0202x over previous
#include <cuda_runtime.h>
#include <cuda_fp16.h>
#include <cstdint>

// SpikingMLP, statically-fused tail-overlap version:
//   pack_all: x -> fp16 hi/lo frags, w_up*2^8 -> fp16 hi/lo, w_down*2^4 -> fp16
//   tc_both (grid 1280, one tile per CTA):
//     bid <  1024: GEMM1 tile (fp16 3-pass) -> rate (exact fp16) + colsum + rowdone
//     bid >= 1024: GEMM2 tile (fp16 1-pass), spins until its row's 32 GEMM1 tiles done
//   finalize_rpu: rate_per_unit = colsum / M (exact).

namespace cfg {
constexpr int M  = 4096;
constexpr int Dd = 1024;
constexpr int Ff = 4096;
}

__device__ uint4 g_axh[(size_t)32 * 32 * 512];
__device__ uint4 g_axl[(size_t)32 * 32 * 512];
__device__ uint4 g_buh[(size_t)32 * 32 * 512];
__device__ uint4 g_bul[(size_t)32 * 32 * 512];
__device__ uint4 g_dw[(size_t)cfg::Dd * cfg::Ff / 8];    // w_down * 2^4
__device__ uint4 g_ratep[(size_t)cfg::M * cfg::Ff / 8];  // rate fp16, GEMM2-A packed
__device__ float g_colsum[cfg::Ff];
__device__ int   g_rowdone[32];

// ------------------------------------------------------------------ helpers
__device__ __forceinline__ uint32_t pack_h2(float a, float b) {
    __half2 p = __floats2half2_rn(a, b);       // .x = a (low half)
    return *(uint32_t*)&p;
}
__device__ __forceinline__ void mma_f16(float c[4], const uint4& a, const uint2& b) {
    asm volatile(
        "mma.sync.aligned.m16n8k16.row.col.f32.f16.f16.f32 "
        "{%0,%1,%2,%3}, {%4,%5,%6,%7}, {%8,%9}, {%0,%1,%2,%3};"
        : "+f"(c[0]), "+f"(c[1]), "+f"(c[2]), "+f"(c[3])
        : "r"(a.x), "r"(a.y), "r"(a.z), "r"(a.w), "r"(b.x), "r"(b.y));
}
__device__ __forceinline__ void cp16(uint32_t sdst, const void* gsrc) {
    asm volatile("cp.async.cg.shared.global [%0], [%1], 16;" :: "r"(sdst), "l"(gsrc));
}
#define CP_COMMIT() asm volatile("cp.async.commit_group;" ::: "memory")
#define CP_WAIT2()  asm volatile("cp.async.wait_group 2;" ::: "memory")

__device__ __forceinline__ float spike_rate_of(float h, float be, int T, float invT) {
    float v = 0.0f; int cnt = 0;
    for (int t = 0; t < T; t++) {
        v = be * v + h;
        if (v > 1.0f) { cnt++; v -= 1.0f; }
    }
    return (float)cnt * invT;
}

// ----------------------------------------------------------- fused pack kernel
// blocks [0,2048): pack x | [2048,6144): pack w_up | [6144,10240): pack w_down
__global__ void pack_all(const float* __restrict__ x,
                         const float* __restrict__ w_up,
                         const float* __restrict__ w_down)
{
    const int bid = blockIdx.x;
    const int tid = threadIdx.x;
    if (bid < 16) g_colsum[bid * 256 + tid] = 0.0f;
    if (bid == 16 && tid < 32) g_rowdone[tid] = 0;

    const int lane = tid & 31;
    const int gq = lane >> 2, tq = lane & 3;

    if (bid < 2048) {                         // ---- x -> A hi/lo frags
        constexpr int K = 1024, KB = K / 16;
        const int wg  = (bid * 256 + tid) >> 5;
        const int rbg = wg / KB, kbg = wg % KB;
        const float* s = x + (size_t)(rbg * 16) * K + kbg * 16;
        float v[8];
        v[0] = s[(size_t)gq * K + 2 * tq];       v[1] = s[(size_t)gq * K + 2 * tq + 1];
        v[2] = s[(size_t)(gq + 8) * K + 2 * tq]; v[3] = s[(size_t)(gq + 8) * K + 2 * tq + 1];
        v[4] = s[(size_t)gq * K + 2 * tq + 8];   v[5] = s[(size_t)gq * K + 2 * tq + 9];
        v[6] = s[(size_t)(gq + 8) * K + 2 * tq + 8]; v[7] = s[(size_t)(gq + 8) * K + 2 * tq + 9];
        float h[8], l[8];
        #pragma unroll
        for (int i = 0; i < 8; i++) {
            h[i] = __half2float(__float2half_rn(v[i]));
            l[i] = v[i] - h[i];
        }
        const int mtile = rbg >> 3, rb = rbg & 7, kc = kbg >> 1, kb = kbg & 1;
        const size_t idx = (((size_t)kc * 32 + mtile) * 16 + rb * 2 + kb) * 32 + lane;
        g_axh[idx] = make_uint4(pack_h2(h[0], h[1]), pack_h2(h[2], h[3]),
                                pack_h2(h[4], h[5]), pack_h2(h[6], h[7]));
        g_axl[idx] = make_uint4(pack_h2(l[0], l[1]), pack_h2(l[2], l[3]),
                                pack_h2(l[4], l[5]), pack_h2(l[6], l[7]));
    } else if (bid < 6144) {                  // ---- w_up * 2^8 -> B hi/lo frags
        constexpr int K = 1024, KB = K / 16;
        const int wg  = ((bid - 2048) * 256 + tid) >> 5;
        const int nbg = wg / KB, kbg = wg % KB;
        const float* s = w_up + (size_t)(nbg * 8 + gq) * K + kbg * 16;
        const float v0 = s[2 * tq] * 256.0f,     v1 = s[2 * tq + 1] * 256.0f;
        const float v2 = s[2 * tq + 8] * 256.0f, v3 = s[2 * tq + 9] * 256.0f;
        const float h0 = __half2float(__float2half_rn(v0));
        const float h1 = __half2float(__float2half_rn(v1));
        const float h2 = __half2float(__float2half_rn(v2));
        const float h3 = __half2float(__float2half_rn(v3));
        const int ntile = nbg >> 4, nb = nbg & 15, kc = kbg >> 1, kb = kbg & 1;
        const size_t idx = ((((size_t)kc * 32 + ntile) * 16 + nb) * 2 + kb) * 32 + lane;
        ((uint2*)g_buh)[idx] = make_uint2(pack_h2(h0, h1), pack_h2(h2, h3));
        ((uint2*)g_bul)[idx] = make_uint2(pack_h2(v0 - h0, v1 - h1), pack_h2(v2 - h2, v3 - h3));
    } else {                                  // ---- w_down * 2^4 -> fp16 frags
        constexpr int K = 4096, KB16 = K / 16;
        const int wg  = ((bid - 6144) * 256 + tid) >> 5;
        const int nbg = wg / KB16, kbg = wg % KB16;
        const float* s = w_down + (size_t)(nbg * 8 + gq) * K + kbg * 16;
        const float v0 = s[2 * tq] * 16.0f,     v1 = s[2 * tq + 1] * 16.0f;
        const float v2 = s[2 * tq + 8] * 16.0f, v3 = s[2 * tq + 9] * 16.0f;
        const int ntile = nbg >> 4, nb = nbg & 15, kc = kbg >> 2, kb = kbg & 3;
        const size_t idx = ((((size_t)kc * 8 + ntile) * 16 + nb) * 4 + kb) * 32 + lane;
        ((uint2*)g_dw)[idx] = make_uint2(pack_h2(v0, v1), pack_h2(v2, v3));
    }
}

__global__ void finalize_rpu(float* __restrict__ rpu) {
    const int f = blockIdx.x * 256 + threadIdx.x;
    rpu[f] = g_colsum[f] * (1.0f / (float)cfg::M);   // exact
}

// ---------------------------------------- fused kernel: one tile per CTA
__global__ __launch_bounds__(256, 2)
void tc_both(const float* __restrict__ beta, const int* __restrict__ Tptr,
             float* __restrict__ C)
{
    extern __shared__ char smc[];
    const int bid = blockIdx.x;
    const int tid = threadIdx.x, lane = tid & 31, wid = tid >> 5;
    const int gq = lane >> 2, tq = lane & 3;
    const int rbb = (wid & 1) * 4, nbb = (wid >> 1) * 4;
    const int wm = (wid & 1) * 64, wn = (wid >> 1) * 32;
    const uint32_t sb = (uint32_t)__cvta_generic_to_shared(smc);

    float acc[4][4][4];                          // shared by both branches
    #pragma unroll
    for (int mi = 0; mi < 4; mi++)
        #pragma unroll
        for (int ni = 0; ni < 4; ni++)
            #pragma unroll
            for (int q = 0; q < 4; q++) acc[mi][ni][q] = 0.0f;

    if (bid < 1024) {
        // ================= GEMM1 tile (R14 body) =================
        constexpr int TILE  = 8192;              // 128x32 fp16
        constexpr int STAGE = 4 * TILE;          // Ah, Al, Bh, Bl
        constexpr int NC    = cfg::Dd / 32;      // 32
        constexpr int STAGES = 3;
        float* sm = (float*)smc;
        const int mtile = bid >> 5, ntile = bid & 31;
        const int colBase = ntile * 128;

        const uint4* pAh = g_axh + (size_t)mtile * 512;
        const uint4* pAl = g_axl + (size_t)mtile * 512;
        const uint4* pBh = g_buh + (size_t)ntile * 512;
        const uint4* pBl = g_bul + (size_t)ntile * 512;
        constexpr size_t strideKC = (size_t)32 * 512;

        auto stage_load = [&](int c, int st) {
            const uint32_t d = sb + (uint32_t)st * STAGE;
            const size_t o = (size_t)c * strideKC;
            #pragma unroll
            for (int q = 0; q < 2; q++) {
                const int idx = q * 256 + tid;
                cp16(d + idx * 16,            pAh + o + idx);
                cp16(d + TILE + idx * 16,     pAl + o + idx);
                cp16(d + 2 * TILE + idx * 16, pBh + o + idx);
                cp16(d + 3 * TILE + idx * 16, pBl + o + idx);
            }
        };

        #pragma unroll
        for (int s = 0; s < STAGES; s++) { stage_load(s, s); CP_COMMIT(); }

        int st = 0;
        for (int c = 0; c < NC; c++) {
            CP_WAIT2();
            __syncthreads();
            const uint4* ahs = (const uint4*)(smc + st * STAGE);
            const uint4* als = (const uint4*)(smc + st * STAGE + TILE);
            const uint2* bhs = (const uint2*)(smc + st * STAGE + 2 * TILE);
            const uint2* bls = (const uint2*)(smc + st * STAGE + 3 * TILE);

            #pragma unroll
            for (int ks = 0; ks < 2; ks++) {
                uint2 bh[4], bl[4];
                #pragma unroll
                for (int ni = 0; ni < 4; ni++) {
                    bh[ni] = bhs[((nbb + ni) * 2 + ks) * 32 + lane];
                    bl[ni] = bls[((nbb + ni) * 2 + ks) * 32 + lane];
                }
                #pragma unroll
                for (int mp = 0; mp < 2; mp++) {
                    const int m0 = 2 * mp, m1 = 2 * mp + 1;
                    const uint4 a0 = ahs[((rbb + m0) * 2 + ks) * 32 + lane];
                    const uint4 a1 = ahs[((rbb + m1) * 2 + ks) * 32 + lane];
                    #pragma unroll
                    for (int ni = 0; ni < 4; ni++) mma_f16(acc[m0][ni], a0, bh[ni]);
                    #pragma unroll
                    for (int ni = 0; ni < 4; ni++) mma_f16(acc[m1][ni], a1, bh[ni]);
                    #pragma unroll
                    for (int ni = 0; ni < 4; ni++) mma_f16(acc[m0][ni], a0, bl[ni]);
                    #pragma unroll
                    for (int ni = 0; ni < 4; ni++) mma_f16(acc[m1][ni], a1, bl[ni]);
                    const uint4 l0 = als[((rbb + m0) * 2 + ks) * 32 + lane];
                    const uint4 l1 = als[((rbb + m1) * 2 + ks) * 32 + lane];
                    #pragma unroll
                    for (int ni = 0; ni < 4; ni++) mma_f16(acc[m0][ni], l0, bh[ni]);
                    #pragma unroll
                    for (int ni = 0; ni < 4; ni++) mma_f16(acc[m1][ni], l1, bh[ni]);
                }
            }
            __syncthreads();
            if (c + STAGES < NC) stage_load(c + STAGES, st);
            CP_COMMIT();
            st = (st + 1 == STAGES) ? 0 : st + 1;
        }

        // epilogue: unscale 2^-8, spike -> smem tile, colsum + fp16 ratep
        constexpr float SC = 1.0f / 256.0f;
        const int   T    = *Tptr;
        const float invT = 1.0f / (float)T;
        __syncthreads();
        #pragma unroll
        for (int ni = 0; ni < 4; ni++) {
            const int cl = wn + ni * 8 + 2 * tq;
            const float be0 = beta[colBase + cl];
            const float be1 = beta[colBase + cl + 1];
            #pragma unroll
            for (int mi = 0; mi < 4; mi++) {
                const int r0 = wm + mi * 16 + gq;
                sm[r0 * 132 + cl]           = spike_rate_of(acc[mi][ni][0] * SC, be0, T, invT);
                sm[r0 * 132 + cl + 1]       = spike_rate_of(acc[mi][ni][1] * SC, be1, T, invT);
                sm[(r0 + 8) * 132 + cl]     = spike_rate_of(acc[mi][ni][2] * SC, be0, T, invT);
                sm[(r0 + 8) * 132 + cl + 1] = spike_rate_of(acc[mi][ni][3] * SC, be1, T, invT);
            }
        }
        __syncthreads();
        if (tid < 128) {
            float s = 0.0f;
            #pragma unroll 8
            for (int r = 0; r < 128; r++) s += sm[r * 132 + tid];
            atomicAdd(&g_colsum[colBase + tid], s);   // exact: multiples of 1/8
        }
        #pragma unroll
        for (int i = 0; i < 8; i++) {
            const int idx = i * 256 + tid;
            const int l2  = idx & 31;
            const int t2  = idx >> 5;
            const int kcj = t2 >> 5;
            const int pos = t2 & 31;
            const int g2 = l2 >> 2, q2 = l2 & 3;
            const int ml = (pos >> 2) * 16;
            const int fl = kcj * 64 + (pos & 3) * 16;
            const int ra = ml + g2, rb2 = ml + g2 + 8;
            const int c0 = fl + 2 * q2, c8 = fl + 2 * q2 + 8;
            uint4 v;
            v.x = pack_h2(sm[ra * 132 + c0],  sm[ra * 132 + c0 + 1]);
            v.y = pack_h2(sm[rb2 * 132 + c0], sm[rb2 * 132 + c0 + 1]);
            v.z = pack_h2(sm[ra * 132 + c8],  sm[ra * 132 + c8 + 1]);
            v.w = pack_h2(sm[rb2 * 132 + c8], sm[rb2 * 132 + c8 + 1]);
            g_ratep[((size_t)(colBase / 64 + kcj) * 32 + mtile) * 1024 + pos * 32 + l2] = v;
        }

        // publish tile, bump row counter
        __threadfence();
        __syncthreads();
        if (tid == 0) atomicAdd(&g_rowdone[mtile], 1);

    } else {
        // ================= GEMM2 tile (R14 body), gated =================
        constexpr int TILE = 16384;              // 128x64 fp16
        constexpr int STAGE = 2 * TILE;
        constexpr int NC = cfg::Ff / 64;         // 64
        constexpr int STAGES = 3;
        const int t = bid - 1024;
        const int mtile = t >> 3, ntile = t & 7;
        const int rowBase = mtile * 128, colBase = ntile * 128;

        if (tid == 0) {
            while (atomicAdd(&g_rowdone[mtile], 0) < 32) __nanosleep(128);
        }
        __syncthreads();
        __threadfence();                         // acquire: row's ratep visible

        const uint4* pA = g_ratep + (size_t)mtile * 1024;
        const uint4* pB = g_dw + (size_t)ntile * 1024;
        constexpr size_t strideA = (size_t)32 * 1024;
        constexpr size_t strideB = (size_t)8 * 1024;

        auto stage_load = [&](int c, int st) {
            const uint32_t d = sb + (uint32_t)st * STAGE;
            const uint4* a = pA + (size_t)c * strideA;
            const uint4* b = pB + (size_t)c * strideB;
            #pragma unroll
            for (int q = 0; q < 4; q++) {
                const int idx = q * 256 + tid;
                cp16(d + idx * 16, a + idx);
                cp16(d + TILE + idx * 16, b + idx);
            }
        };

        #pragma unroll
        for (int s = 0; s < STAGES; s++) { stage_load(s, s); CP_COMMIT(); }

        int st = 0;
        for (int c = 0; c < NC; c++) {
            CP_WAIT2();
            __syncthreads();
            const uint4* ahs = (const uint4*)(smc + st * STAGE);
            const uint2* bhs = (const uint2*)(smc + st * STAGE + TILE);

            #pragma unroll
            for (int ks = 0; ks < 4; ks++) {
                uint2 bh[4];
                #pragma unroll
                for (int ni = 0; ni < 4; ni++)
                    bh[ni] = bhs[((nbb + ni) * 4 + ks) * 32 + lane];
                #pragma unroll
                for (int mp = 0; mp < 2; mp++) {
                    const int m0 = 2 * mp, m1 = 2 * mp + 1;
                    const uint4 a0 = ahs[((rbb + m0) * 4 + ks) * 32 + lane];
                    const uint4 a1 = ahs[((rbb + m1) * 4 + ks) * 32 + lane];
                    #pragma unroll
                    for (int ni = 0; ni < 4; ni++) mma_f16(acc[m0][ni], a0, bh[ni]);
                    #pragma unroll
                    for (int ni = 0; ni < 4; ni++) mma_f16(acc[m1][ni], a1, bh[ni]);
                }
            }
            __syncthreads();
            if (c + STAGES < NC) stage_load(c + STAGES, st);
            CP_COMMIT();
            st = (st + 1 == STAGES) ? 0 : st + 1;
        }

        constexpr float SC = 1.0f / 16.0f;       // exact unscale of w_down*16
        #pragma unroll
        for (int ni = 0; ni < 4; ni++) {
            const int cglob = colBase + wn + ni * 8 + 2 * tq;
            #pragma unroll
            for (int mi = 0; mi < 4; mi++) {
                const int r0 = rowBase + wm + mi * 16 + gq;
                *(float2*)(C + (size_t)r0 * cfg::Dd + cglob) =
                    make_float2(acc[mi][ni][0] * SC, acc[mi][ni][1] * SC);
                *(float2*)(C + (size_t)(r0 + 8) * cfg::Dd + cglob) =
                    make_float2(acc[mi][ni][2] * SC, acc[mi][ni][3] * SC);
            }
        }
    }
}

// -------------------------------------------------------------------- launch
extern "C" void kernel_launch(void* const* d_in, const int* in_sizes, int n_in,
                              void* d_out, int out_size)
{
    const float* x      = (const float*)d_in[0];
    const float* w_up   = (const float*)d_in[1];
    const float* w_down = (const float*)d_in[2];
    const float* beta   = (const float*)d_in[3];
    const int*   Tptr   = (const int*)d_in[4];

    float* out = (float*)d_out;
    float* rpu = out + (size_t)cfg::M * cfg::Dd;

    pack_all<<<10240, 256>>>(x, w_up, w_down);

    constexpr int SMEM = 98304;   // 96 KB for both tile kinds
    cudaFuncSetAttribute(tc_both, cudaFuncAttributeMaxDynamicSharedMemorySize, SMEM);

    tc_both<<<1280, 256, SMEM>>>(beta, Tptr, out);

    finalize_rpu<<<cfg::Ff / 256, 256>>>(rpu);
}